// round 5
// baseline (speedup 1.0000x reference)
#include <cuda_runtime.h>
#include <stdint.h>
#include <stddef.h>

#define NN   100000
#define FIN  128
#define HD   64
#define CD   40

// ---------------- scratch (static device globals; no allocation) ----------------
__device__ float g_dinv[NN];
__device__ float g_h1  [(size_t)NN * HD];   // x@W1, later reused for dropout output
__device__ float g_agg1[(size_t)NN * HD];
__device__ float g_h2t [(size_t)NN * CD];

// ---------------- threefry2x32 (bit-exact JAX; verified vs Random123 KAT) ----------------
__device__ __forceinline__ uint32_t rotl32(uint32_t x, int d) {
    return __funnelshift_l(x, x, d);
}
__device__ __forceinline__ void tf_round(uint32_t& x0, uint32_t& x1, int r) {
    x0 += x1; x1 = rotl32(x1, r); x1 ^= x0;
}
__device__ __forceinline__ uint2 threefry_0_42(uint32_t x0, uint32_t x1) {
    const uint32_t k0 = 0u, k1 = 42u;
    const uint32_t k2 = 0u ^ 42u ^ 0x1BD11BDAu;
    x0 += k0; x1 += k1;
    tf_round(x0,x1,13); tf_round(x0,x1,15); tf_round(x0,x1,26); tf_round(x0,x1,6);
    x0 += k1; x1 += k2 + 1u;
    tf_round(x0,x1,17); tf_round(x0,x1,29); tf_round(x0,x1,16); tf_round(x0,x1,24);
    x0 += k2; x1 += k0 + 2u;
    tf_round(x0,x1,13); tf_round(x0,x1,15); tf_round(x0,x1,26); tf_round(x0,x1,6);
    x0 += k0; x1 += k1 + 3u;
    tf_round(x0,x1,17); tf_round(x0,x1,29); tf_round(x0,x1,16); tf_round(x0,x1,24);
    x0 += k1; x1 += k2 + 4u;
    tf_round(x0,x1,13); tf_round(x0,x1,15); tf_round(x0,x1,26); tf_round(x0,x1,6);
    x0 += k2; x1 += k0 + 5u;
    return make_uint2(x0, x1);
}

// ---------------- degree ----------------
__global__ void deg_init_kernel(float* __restrict__ deg, int n) {
    int i = blockIdx.x * blockDim.x + threadIdx.x;
    if (i < n) deg[i] = 1.0f;   // self loop
}
__global__ void deg_count_kernel(const int* __restrict__ col, float* __restrict__ deg, int E) {
    int i = blockIdx.x * blockDim.x + threadIdx.x;
    if (i < E) atomicAdd(&deg[col[i]], 1.0f);
}
__global__ void deg_fin_kernel(float* __restrict__ deg, int n) {
    int i = blockIdx.x * blockDim.x + threadIdx.x;
    if (i < n) deg[i] = (float)(1.0 / sqrt((double)deg[i]));   // deg >= 1 always
}

// ---------------- tiled fp32 GEMM: Y[n,DOUT] = X[n,DIN] @ W[DIN,DOUT] ----------------
template<int DIN, int DOUT>
__launch_bounds__(256)
__global__ void gemm_kernel(const float* __restrict__ X, const float* __restrict__ W,
                            float* __restrict__ Y, int n) {
    constexpr int BM = 32;
    __shared__ float sXT[DIN][BM];   // transposed X tile
    __shared__ float sW [DIN][DOUT];

    const int m0  = blockIdx.x * BM;
    const int tid = threadIdx.x;

    constexpr int WV = DIN * DOUT / 4;
    for (int i = tid; i < WV; i += 256)
        ((float4*)sW)[i] = ((const float4*)W)[i];

    constexpr int KV  = DIN / 4;
    constexpr int RPP = 256 / KV;
    {
        int r  = tid / KV;
        int kv = (tid % KV) * 4;
        for (int rr = r; rr < BM; rr += RPP) {
            int row = m0 + rr;
            float4 v;
            if (row < n) v = *(const float4*)&X[(size_t)row * DIN + kv];
            else         v = make_float4(0.f, 0.f, 0.f, 0.f);
            sXT[kv+0][rr] = v.x; sXT[kv+1][rr] = v.y;
            sXT[kv+2][rr] = v.z; sXT[kv+3][rr] = v.w;
        }
    }
    __syncthreads();

    const int tx = tid & 15, ty = tid >> 4;
    const int c0 = tx * 4;
    if (c0 < DOUT) {
        const int r0 = ty * 2;
        float a00=0.f,a01=0.f,a02=0.f,a03=0.f;
        float a10=0.f,a11=0.f,a12=0.f,a13=0.f;
        #pragma unroll 8
        for (int k = 0; k < DIN; k++) {
            float4 wv = *(const float4*)&sW[k][c0];
            float x0 = sXT[k][r0], x1 = sXT[k][r0 + 1];
            a00 += x0*wv.x; a01 += x0*wv.y; a02 += x0*wv.z; a03 += x0*wv.w;
            a10 += x1*wv.x; a11 += x1*wv.y; a12 += x1*wv.z; a13 += x1*wv.w;
        }
        int row = m0 + r0;
        if (row < n)
            *(float4*)&Y[(size_t)row * DOUT + c0] = make_float4(a00, a01, a02, a03);
        if (row + 1 < n)
            *(float4*)&Y[(size_t)(row + 1) * DOUT + c0] = make_float4(a10, a11, a12, a13);
    }
}

// ---------------- aggregation init: agg = b + dinv^2 * h (self loop + bias) ----------------
template<int D>
__global__ void agg_init_kernel(const float* __restrict__ h, const float* __restrict__ bias,
                                const float* __restrict__ dinv, float* __restrict__ agg,
                                int total) {
    int idx = blockIdx.x * blockDim.x + threadIdx.x;
    if (idx >= total) return;
    int node = idx / D;
    int f    = idx - node * D;
    float w = dinv[node];
    agg[idx] = bias[f] + w * w * h[idx];
}

// ---------------- edge scatter: agg[col] += dinv[row]*dinv[col] * h[row] ----------------
template<int D>
__global__ void scatter_kernel(const int* __restrict__ row, const int* __restrict__ col,
                               const float* __restrict__ dinv, const float* __restrict__ h,
                               float* __restrict__ agg, int E) {
    constexpr int F4 = D / 4;
    int idx = blockIdx.x * blockDim.x + threadIdx.x;
    int e = idx / F4;
    if (e >= E) return;
    int f = (idx - e * F4) * 4;
    int r = row[e], c = col[e];
    float w = dinv[r] * dinv[c];
    float4 v = *(const float4*)&h[(size_t)r * D + f];
    float* dst = &agg[(size_t)c * D + f];
    atomicAdd(dst + 0, v.x * w);
    atomicAdd(dst + 1, v.y * w);
    atomicAdd(dst + 2, v.z * w);
    atomicAdd(dst + 3, v.w * w);
}

// ---------------- relu + deterministic dropout ----------------
// jax_threefry_partitionable=True, bit_width=32 path in _threefry_random_bits_partitionable:
//   counter64[i] = i ; (x1, x2) = (uint32(i >> 32), uint32(i)) = (0, i)  since S < 2^32
//   (bits1, bits2) = threefry2x32((0,42), x1, x2)
//   bits32 = bits1 ^ bits2            <-- sub-64-bit widths XOR the two lanes
//   u = bitcast_f32((bits32 >> 9) | 0x3f800000) - 1.0f ;  mask = u < (1-0.4144)f32
__global__ void relu_dropout_kernel(const float* __restrict__ agg, float* __restrict__ out,
                                    int total) {
    int i = blockIdx.x * blockDim.x + threadIdx.x;
    if (i >= total) return;
    uint2 rnd = threefry_0_42(0u, (uint32_t)i);
    uint32_t bits = rnd.x ^ rnd.y;   // lane0 ^ lane1
    float u = __uint_as_float((bits >> 9) | 0x3f800000u) - 1.0f;
    const float KEEP = (float)(1.0 - 0.4144);
    float v = agg[i];
    v = fmaxf(v, 0.0f);
    out[i] = (u < KEEP) ? (v / KEEP) : 0.0f;
}

// ---------------- log_softmax over C=40, in place, one warp per node ----------------
__global__ void log_softmax_kernel(float* __restrict__ y, int n) {
    int gw   = (blockIdx.x * blockDim.x + threadIdx.x) >> 5;
    int lane = threadIdx.x & 31;
    if (gw >= n) return;
    float* p = y + (size_t)gw * CD;
    float v0 = p[lane];
    float v1 = (lane + 32 < CD) ? p[lane + 32] : -3.4e38f;
    float m = fmaxf(v0, v1);
    #pragma unroll
    for (int o = 16; o; o >>= 1) m = fmaxf(m, __shfl_xor_sync(0xffffffffu, m, o));
    float s = expf(v0 - m)
            + ((lane + 32 < CD) ? expf(v1 - m) : 0.0f);
    #pragma unroll
    for (int o = 16; o; o >>= 1) s += __shfl_xor_sync(0xffffffffu, s, o);
    float ls = logf(s);
    p[lane] = v0 - m - ls;
    if (lane + 32 < CD) p[lane + 32] = v1 - m - ls;
}

// ---------------- launch ----------------
extern "C" void kernel_launch(void* const* d_in, const int* in_sizes, int n_in,
                              void* d_out, int out_size) {
    const float* x  = (const float*)d_in[0];
    const int*   ei = (const int*)  d_in[1];
    const float* W1 = (const float*)d_in[2];
    const float* b1 = (const float*)d_in[3];
    const float* W2 = (const float*)d_in[4];
    const float* b2 = (const float*)d_in[5];
    float* out = (float*)d_out;

    const int n = NN;
    const int E = in_sizes[1] / 2;
    const int* row = ei;
    const int* col = ei + E;

    float *dinv, *h1, *agg1, *h2t;
    cudaGetSymbolAddress((void**)&dinv, g_dinv);
    cudaGetSymbolAddress((void**)&h1,   g_h1);
    cudaGetSymbolAddress((void**)&agg1, g_agg1);
    cudaGetSymbolAddress((void**)&h2t,  g_h2t);

    const int T = 256;
    auto cdiv = [](long long a, long long b) { return (int)((a + b - 1) / b); };

    // degree
    deg_init_kernel <<<cdiv(n, T), T>>>(dinv, n);
    deg_count_kernel<<<cdiv(E, T), T>>>(col, dinv, E);
    deg_fin_kernel  <<<cdiv(n, T), T>>>(dinv, n);

    // layer 1
    gemm_kernel<FIN, HD><<<cdiv(n, 32), T>>>(x, W1, h1, n);
    agg_init_kernel<HD><<<cdiv((long long)n * HD, T), T>>>(h1, b1, dinv, agg1, n * HD);
    scatter_kernel<HD><<<cdiv((long long)E * (HD / 4), T), T>>>(row, col, dinv, h1, agg1, E);

    // relu + dropout (writes back into h1 buffer)
    relu_dropout_kernel<<<cdiv((long long)n * HD, T), T>>>(agg1, h1, n * HD);

    // layer 2 (aggregate straight into d_out)
    gemm_kernel<HD, CD><<<cdiv(n, 32), T>>>(h1, W2, h2t, n);
    agg_init_kernel<CD><<<cdiv((long long)n * CD, T), T>>>(h2t, b2, dinv, out, n * CD);
    scatter_kernel<CD><<<cdiv((long long)E * (CD / 4), T), T>>>(row, col, dinv, h2t, out, E);

    // log softmax in place
    log_softmax_kernel<<<cdiv((long long)n * 32, T), T>>>(out, n);
}

// round 7
// speedup vs baseline: 1.6872x; 1.6872x over previous
#include <cuda_runtime.h>
#include <stdint.h>
#include <stddef.h>

#define NN    100000
#define EMAX  1600000
#define FIN   128
#define HD    64
#define CD    40

#define SCAN_BS   512
#define NB1       ((NN + SCAN_BS - 1) / SCAN_BS)   // 196

// ---------------- scratch (static device globals; no allocation) ----------------
__device__ float g_dinv[NN];
__device__ int   g_cnt [NN];
__device__ int   g_rowptr[NN + 1];
__device__ int   g_cursor[NN];
__device__ int   g_bsum[NB1 + 1];
__device__ int   g_esrc[EMAX];
__device__ float g_ewgt[EMAX];
__device__ float g_h1  [(size_t)NN * HD];
__device__ float g_agg1[(size_t)NN * HD];
__device__ float g_h2t [(size_t)NN * CD];

// ---------------- threefry2x32 (bit-exact JAX partitionable path) ----------------
__device__ __forceinline__ uint32_t rotl32(uint32_t x, int d) {
    return __funnelshift_l(x, x, d);
}
__device__ __forceinline__ void tf_round(uint32_t& x0, uint32_t& x1, int r) {
    x0 += x1; x1 = rotl32(x1, r); x1 ^= x0;
}
__device__ __forceinline__ uint2 threefry_0_42(uint32_t x0, uint32_t x1) {
    const uint32_t k0 = 0u, k1 = 42u;
    const uint32_t k2 = 0u ^ 42u ^ 0x1BD11BDAu;
    x0 += k0; x1 += k1;
    tf_round(x0,x1,13); tf_round(x0,x1,15); tf_round(x0,x1,26); tf_round(x0,x1,6);
    x0 += k1; x1 += k2 + 1u;
    tf_round(x0,x1,17); tf_round(x0,x1,29); tf_round(x0,x1,16); tf_round(x0,x1,24);
    x0 += k2; x1 += k0 + 2u;
    tf_round(x0,x1,13); tf_round(x0,x1,15); tf_round(x0,x1,26); tf_round(x0,x1,6);
    x0 += k0; x1 += k1 + 3u;
    tf_round(x0,x1,17); tf_round(x0,x1,29); tf_round(x0,x1,16); tf_round(x0,x1,24);
    x0 += k1; x1 += k2 + 4u;
    tf_round(x0,x1,13); tf_round(x0,x1,15); tf_round(x0,x1,26); tf_round(x0,x1,6);
    x0 += k2; x1 += k0 + 5u;
    return make_uint2(x0, x1);
}

// ---------------- CSR build ----------------
__global__ void hist_kernel(const int* __restrict__ col, int* __restrict__ cnt, int E) {
    int i = blockIdx.x * blockDim.x + threadIdx.x;
    if (i < E) atomicAdd(&cnt[col[i]], 1);
}
__global__ void dinv_kernel(const int* __restrict__ cnt, float* __restrict__ dinv, int n) {
    int i = blockIdx.x * blockDim.x + threadIdx.x;
    if (i < n) dinv[i] = (float)(1.0 / sqrt((double)(cnt[i] + 1)));   // +1 self loop
}
// per-block exclusive scan (512 elems/block) + block sums
__global__ void scan1_kernel(const int* __restrict__ cnt, int* __restrict__ rowptr,
                             int* __restrict__ bsum, int n) {
    __shared__ int s[SCAN_BS];
    int tid = threadIdx.x;
    int gid = blockIdx.x * SCAN_BS + tid;
    int v = (gid < n) ? cnt[gid] : 0;
    s[tid] = v;
    __syncthreads();
    // Hillis-Steele inclusive scan
    #pragma unroll
    for (int off = 1; off < SCAN_BS; off <<= 1) {
        int t = (tid >= off) ? s[tid - off] : 0;
        __syncthreads();
        s[tid] += t;
        __syncthreads();
    }
    if (gid < n) rowptr[gid] = s[tid] - v;       // exclusive (block-local)
    if (tid == SCAN_BS - 1) bsum[blockIdx.x] = s[tid];
}
__global__ void scan2_kernel(int* __restrict__ bsum, int nb) {
    __shared__ int s[256];
    int tid = threadIdx.x;
    int v = (tid < nb) ? bsum[tid] : 0;
    s[tid] = v;
    __syncthreads();
    #pragma unroll
    for (int off = 1; off < 256; off <<= 1) {
        int t = (tid >= off) ? s[tid - off] : 0;
        __syncthreads();
        s[tid] += t;
        __syncthreads();
    }
    if (tid < nb) bsum[tid] = s[tid] - v;        // exclusive
}
__global__ void scan3_kernel(int* __restrict__ rowptr, int* __restrict__ cursor,
                             const int* __restrict__ bsum, int n, int E) {
    int i = blockIdx.x * blockDim.x + threadIdx.x;
    if (i < n) {
        int r = rowptr[i] + bsum[i / SCAN_BS];
        rowptr[i] = r;
        cursor[i] = r;
    }
    if (i == 0) rowptr[n] = E;
}
__global__ void fill_kernel(const int* __restrict__ row, const int* __restrict__ col,
                            const float* __restrict__ dinv,
                            int* __restrict__ cursor, int* __restrict__ esrc,
                            float* __restrict__ ewgt, int E) {
    int e = blockIdx.x * blockDim.x + threadIdx.x;
    if (e >= E) return;
    int r = row[e], c = col[e];
    int pos = atomicAdd(&cursor[c], 1);
    esrc[pos] = r;
    ewgt[pos] = dinv[r];
}

// ---------------- tiled fp32 GEMM: Y[n,DOUT] = X[n,DIN] @ W[DIN,DOUT] ----------------
template<int DIN, int DOUT>
__launch_bounds__(256)
__global__ void gemm_kernel(const float* __restrict__ X, const float* __restrict__ W,
                            float* __restrict__ Y, int n) {
    constexpr int BM = 32;
    __shared__ float sXT[DIN][BM];
    __shared__ float sW [DIN][DOUT];

    const int m0  = blockIdx.x * BM;
    const int tid = threadIdx.x;

    constexpr int WV = DIN * DOUT / 4;
    for (int i = tid; i < WV; i += 256)
        ((float4*)sW)[i] = ((const float4*)W)[i];

    constexpr int KV  = DIN / 4;
    constexpr int RPP = 256 / KV;
    {
        int r  = tid / KV;
        int kv = (tid % KV) * 4;
        for (int rr = r; rr < BM; rr += RPP) {
            int row = m0 + rr;
            float4 v;
            if (row < n) v = *(const float4*)&X[(size_t)row * DIN + kv];
            else         v = make_float4(0.f, 0.f, 0.f, 0.f);
            sXT[kv+0][rr] = v.x; sXT[kv+1][rr] = v.y;
            sXT[kv+2][rr] = v.z; sXT[kv+3][rr] = v.w;
        }
    }
    __syncthreads();

    const int tx = tid & 15, ty = tid >> 4;
    const int c0 = tx * 4;
    if (c0 < DOUT) {
        const int r0 = ty * 2;
        float a00=0.f,a01=0.f,a02=0.f,a03=0.f;
        float a10=0.f,a11=0.f,a12=0.f,a13=0.f;
        #pragma unroll 8
        for (int k = 0; k < DIN; k++) {
            float4 wv = *(const float4*)&sW[k][c0];
            float x0 = sXT[k][r0], x1 = sXT[k][r0 + 1];
            a00 += x0*wv.x; a01 += x0*wv.y; a02 += x0*wv.z; a03 += x0*wv.w;
            a10 += x1*wv.x; a11 += x1*wv.y; a12 += x1*wv.z; a13 += x1*wv.w;
        }
        int row = m0 + r0;
        if (row < n)
            *(float4*)&Y[(size_t)row * DOUT + c0] = make_float4(a00, a01, a02, a03);
        if (row + 1 < n)
            *(float4*)&Y[(size_t)(row + 1) * DOUT + c0] = make_float4(a10, a11, a12, a13);
    }
}

// ---------------- pull aggregation: one warp per node ----------------
// out[node] = bias + dinv[node]^2 * h[node] + sum_j ewgt[j]*dinv[node] * h[esrc[j]]
__global__ __launch_bounds__(256)
void pull64_kernel(const int* __restrict__ rowptr, const int* __restrict__ esrc,
                   const float* __restrict__ ewgt, const float* __restrict__ dinv,
                   const float* __restrict__ h, const float* __restrict__ bias,
                   float* __restrict__ out, int n) {
    int wid  = (blockIdx.x * blockDim.x + threadIdx.x) >> 5;
    int lane = threadIdx.x & 31;
    if (wid >= n) return;
    const int node = wid;
    const int f = lane * 2;
    float wn = dinv[node];
    float2 acc = *(const float2*)&bias[f];
    float2 hv  = *(const float2*)&h[(size_t)node * HD + f];
    acc.x += wn * wn * hv.x;
    acc.y += wn * wn * hv.y;
    int s = rowptr[node], e = rowptr[node + 1];
    for (int j = s; j < e; j++) {
        int   src = esrc[j];
        float w   = ewgt[j] * wn;
        float2 v  = *(const float2*)&h[(size_t)src * HD + f];
        acc.x += w * v.x;
        acc.y += w * v.y;
    }
    *(float2*)&out[(size_t)node * HD + f] = acc;
}

__global__ __launch_bounds__(256)
void pull40_kernel(const int* __restrict__ rowptr, const int* __restrict__ esrc,
                   const float* __restrict__ ewgt, const float* __restrict__ dinv,
                   const float* __restrict__ h, const float* __restrict__ bias,
                   float* __restrict__ out, int n) {
    int wid  = (blockIdx.x * blockDim.x + threadIdx.x) >> 5;
    int lane = threadIdx.x & 31;
    if (wid >= n) return;
    const int node = wid;
    const bool act = lane < CD / 2;     // 20 active lanes, float2 each
    const int f = lane * 2;
    float wn = dinv[node];
    float2 acc = make_float2(0.f, 0.f);
    if (act) {
        acc = *(const float2*)&bias[f];
        float2 hv = *(const float2*)&h[(size_t)node * CD + f];
        acc.x += wn * wn * hv.x;
        acc.y += wn * wn * hv.y;
    }
    int s = rowptr[node], e = rowptr[node + 1];
    for (int j = s; j < e; j++) {
        int   src = esrc[j];
        float w   = ewgt[j] * wn;
        if (act) {
            float2 v = *(const float2*)&h[(size_t)src * CD + f];
            acc.x += w * v.x;
            acc.y += w * v.y;
        }
    }
    if (act) *(float2*)&out[(size_t)node * CD + f] = acc;
}

// ---------------- relu + deterministic dropout (partitionable threefry, XOR fold) ----------------
__global__ void relu_dropout_kernel(const float* __restrict__ agg, float* __restrict__ out,
                                    int total) {
    int i = blockIdx.x * blockDim.x + threadIdx.x;
    if (i >= total) return;
    uint2 rnd = threefry_0_42(0u, (uint32_t)i);
    uint32_t bits = rnd.x ^ rnd.y;
    float u = __uint_as_float((bits >> 9) | 0x3f800000u) - 1.0f;
    const float KEEP = (float)(1.0 - 0.4144);
    float v = agg[i];
    v = fmaxf(v, 0.0f);
    out[i] = (u < KEEP) ? (v / KEEP) : 0.0f;
}

// ---------------- log_softmax over C=40, in place, one warp per node ----------------
__global__ void log_softmax_kernel(float* __restrict__ y, int n) {
    int gw   = (blockIdx.x * blockDim.x + threadIdx.x) >> 5;
    int lane = threadIdx.x & 31;
    if (gw >= n) return;
    float* p = y + (size_t)gw * CD;
    float v0 = p[lane];
    float v1 = (lane + 32 < CD) ? p[lane + 32] : -3.4e38f;
    float m = fmaxf(v0, v1);
    #pragma unroll
    for (int o = 16; o; o >>= 1) m = fmaxf(m, __shfl_xor_sync(0xffffffffu, m, o));
    float s = expf(v0 - m)
            + ((lane + 32 < CD) ? expf(v1 - m) : 0.0f);
    #pragma unroll
    for (int o = 16; o; o >>= 1) s += __shfl_xor_sync(0xffffffffu, s, o);
    float ls = logf(s);
    p[lane] = v0 - m - ls;
    if (lane + 32 < CD) p[lane + 32] = v1 - m - ls;
}

// ---------------- launch ----------------
extern "C" void kernel_launch(void* const* d_in, const int* in_sizes, int n_in,
                              void* d_out, int out_size) {
    const float* x  = (const float*)d_in[0];
    const int*   ei = (const int*)  d_in[1];
    const float* W1 = (const float*)d_in[2];
    const float* b1 = (const float*)d_in[3];
    const float* W2 = (const float*)d_in[4];
    const float* b2 = (const float*)d_in[5];
    float* out = (float*)d_out;

    const int n = NN;
    const int E = in_sizes[1] / 2;
    const int* row = ei;
    const int* col = ei + E;

    float *dinv, *h1, *agg1, *h2t, *ewgt;
    int *cnt, *rowptr, *cursor, *bsum, *esrc;
    cudaGetSymbolAddress((void**)&dinv,   g_dinv);
    cudaGetSymbolAddress((void**)&cnt,    g_cnt);
    cudaGetSymbolAddress((void**)&rowptr, g_rowptr);
    cudaGetSymbolAddress((void**)&cursor, g_cursor);
    cudaGetSymbolAddress((void**)&bsum,   g_bsum);
    cudaGetSymbolAddress((void**)&esrc,   g_esrc);
    cudaGetSymbolAddress((void**)&ewgt,   g_ewgt);
    cudaGetSymbolAddress((void**)&h1,     g_h1);
    cudaGetSymbolAddress((void**)&agg1,   g_agg1);
    cudaGetSymbolAddress((void**)&h2t,    g_h2t);

    const int T = 256;
    auto cdiv = [](long long a, long long b) { return (int)((a + b - 1) / b); };

    // ---- CSR build (also yields degree/dinv) ----
    cudaMemsetAsync(cnt, 0, NN * sizeof(int));
    hist_kernel <<<cdiv(E, T), T>>>(col, cnt, E);
    dinv_kernel <<<cdiv(n, T), T>>>(cnt, dinv, n);
    scan1_kernel<<<NB1, SCAN_BS>>>(cnt, rowptr, bsum, n);
    scan2_kernel<<<1, 256>>>(bsum, NB1);
    scan3_kernel<<<cdiv(n, T), T>>>(rowptr, cursor, bsum, n, E);
    fill_kernel <<<cdiv(E, T), T>>>(row, col, dinv, cursor, esrc, ewgt, E);

    // ---- layer 1: gemm + pull (bias & self-loop fused) ----
    gemm_kernel<FIN, HD><<<cdiv(n, 32), T>>>(x, W1, h1, n);
    pull64_kernel<<<cdiv((long long)n * 32, T), T>>>(rowptr, esrc, ewgt, dinv, h1, b1, agg1, n);

    // ---- relu + dropout (into h1 buffer) ----
    relu_dropout_kernel<<<cdiv((long long)n * HD, T), T>>>(agg1, h1, n * HD);

    // ---- layer 2: gemm + pull straight into d_out ----
    gemm_kernel<HD, CD><<<cdiv(n, 32), T>>>(h1, W2, h2t, n);
    pull40_kernel<<<cdiv((long long)n * 32, T), T>>>(rowptr, esrc, ewgt, dinv, h2t, b2, out, n);

    // ---- log softmax in place ----
    log_softmax_kernel<<<cdiv((long long)n * 32, T), T>>>(out, n);
}

// round 8
// speedup vs baseline: 2.2616x; 1.3404x over previous
#include <cuda_runtime.h>
#include <stdint.h>
#include <stddef.h>

#define NN    100000
#define EMAX  1600000
#define FIN   128
#define HD    64
#define CD    40

#define SCAN_BS   512
#define NB1       ((NN + SCAN_BS - 1) / SCAN_BS)   // 196

// ---------------- scratch (static device globals; no allocation) ----------------
__device__ float g_dinv[NN];
__device__ int   g_cnt [NN];
__device__ int   g_rowptr[NN + 1];
__device__ int   g_cursor[NN];
__device__ int   g_bsum[NB1 + 1];
__device__ int   g_esrc[EMAX];
__device__ float g_ewgt[EMAX];
__device__ float g_h1  [(size_t)NN * HD];   // gemm1 out
__device__ float g_agg1[(size_t)NN * HD];   // pull64 + relu + dropout out
__device__ float g_h2t [(size_t)NN * CD];   // gemm2 out

// ---------------- threefry2x32 (bit-exact JAX partitionable path) ----------------
__device__ __forceinline__ uint32_t rotl32(uint32_t x, int d) {
    return __funnelshift_l(x, x, d);
}
__device__ __forceinline__ void tf_round(uint32_t& x0, uint32_t& x1, int r) {
    x0 += x1; x1 = rotl32(x1, r); x1 ^= x0;
}
__device__ __forceinline__ uint2 threefry_0_42(uint32_t x0, uint32_t x1) {
    const uint32_t k0 = 0u, k1 = 42u;
    const uint32_t k2 = 0u ^ 42u ^ 0x1BD11BDAu;
    x0 += k0; x1 += k1;
    tf_round(x0,x1,13); tf_round(x0,x1,15); tf_round(x0,x1,26); tf_round(x0,x1,6);
    x0 += k1; x1 += k2 + 1u;
    tf_round(x0,x1,17); tf_round(x0,x1,29); tf_round(x0,x1,16); tf_round(x0,x1,24);
    x0 += k2; x1 += k0 + 2u;
    tf_round(x0,x1,13); tf_round(x0,x1,15); tf_round(x0,x1,26); tf_round(x0,x1,6);
    x0 += k0; x1 += k1 + 3u;
    tf_round(x0,x1,17); tf_round(x0,x1,29); tf_round(x0,x1,16); tf_round(x0,x1,24);
    x0 += k1; x1 += k2 + 4u;
    tf_round(x0,x1,13); tf_round(x0,x1,15); tf_round(x0,x1,26); tf_round(x0,x1,6);
    x0 += k2; x1 += k0 + 5u;
    return make_uint2(x0, x1);
}
__device__ __forceinline__ float dropout_scale_42(uint32_t i, float v) {
    // relu already applied by caller. mask = u < (1-0.4144) with JAX f32 uniform.
    uint2 rnd = threefry_0_42(0u, i);
    uint32_t bits = rnd.x ^ rnd.y;
    float u = __uint_as_float((bits >> 9) | 0x3f800000u) - 1.0f;
    const float KEEP = (float)(1.0 - 0.4144);
    return (u < KEEP) ? (v / KEEP) : 0.0f;
}

// ---------------- CSR build ----------------
__global__ void hist_kernel(const int* __restrict__ col, int* __restrict__ cnt, int E) {
    int i = blockIdx.x * blockDim.x + threadIdx.x;
    if (i < E) atomicAdd(&cnt[col[i]], 1);
}
__global__ void dinv_kernel(const int* __restrict__ cnt, float* __restrict__ dinv, int n) {
    int i = blockIdx.x * blockDim.x + threadIdx.x;
    if (i < n) dinv[i] = (float)(1.0 / sqrt((double)(cnt[i] + 1)));   // +1 self loop
}
__global__ void scan1_kernel(const int* __restrict__ cnt, int* __restrict__ rowptr,
                             int* __restrict__ bsum, int n) {
    __shared__ int s[SCAN_BS];
    int tid = threadIdx.x;
    int gid = blockIdx.x * SCAN_BS + tid;
    int v = (gid < n) ? cnt[gid] : 0;
    s[tid] = v;
    __syncthreads();
    #pragma unroll
    for (int off = 1; off < SCAN_BS; off <<= 1) {
        int t = (tid >= off) ? s[tid - off] : 0;
        __syncthreads();
        s[tid] += t;
        __syncthreads();
    }
    if (gid < n) rowptr[gid] = s[tid] - v;
    if (tid == SCAN_BS - 1) bsum[blockIdx.x] = s[tid];
}
__global__ void scan2_kernel(int* __restrict__ bsum, int nb) {
    __shared__ int s[256];
    int tid = threadIdx.x;
    int v = (tid < nb) ? bsum[tid] : 0;
    s[tid] = v;
    __syncthreads();
    #pragma unroll
    for (int off = 1; off < 256; off <<= 1) {
        int t = (tid >= off) ? s[tid - off] : 0;
        __syncthreads();
        s[tid] += t;
        __syncthreads();
    }
    if (tid < nb) bsum[tid] = s[tid] - v;
}
__global__ void scan3_kernel(int* __restrict__ rowptr, int* __restrict__ cursor,
                             const int* __restrict__ bsum, int n, int E) {
    int i = blockIdx.x * blockDim.x + threadIdx.x;
    if (i < n) {
        int r = rowptr[i] + bsum[i / SCAN_BS];
        rowptr[i] = r;
        cursor[i] = r;
    }
    if (i == 0) rowptr[n] = E;
}
__global__ void fill_kernel(const int* __restrict__ row, const int* __restrict__ col,
                            const float* __restrict__ dinv,
                            int* __restrict__ cursor, int* __restrict__ esrc,
                            float* __restrict__ ewgt, int E) {
    int e = blockIdx.x * blockDim.x + threadIdx.x;
    if (e >= E) return;
    int r = row[e], c = col[e];
    int pos = atomicAdd(&cursor[c], 1);
    esrc[pos] = r;
    ewgt[pos] = dinv[r];
}

// ---------------- GEMM1: Y[n,64] = X[n,128] @ W[128,64], 4x4 register tile ----------------
// BM=32 rows/block, 128 threads (16 tx x 8 ty), thread computes 4 rows x 4 cols.
__global__ __launch_bounds__(128)
void gemm1_kernel(const float* __restrict__ X, const float* __restrict__ W,
                  float* __restrict__ Y, int n) {
    __shared__ float sX[32][FIN];    // row-major X tile, 16KB
    __shared__ float sW[FIN][HD];    // 32KB  (total 48KB exactly)
    const int tid = threadIdx.x;
    const int m0  = blockIdx.x * 32;

    for (int i = tid; i < FIN * HD / 4; i += 128)
        ((float4*)sW)[i] = ((const float4*)W)[i];
    {
        int r  = tid >> 5;            // 0..3
        int kv = (tid & 31) * 4;
        #pragma unroll
        for (int rr = r; rr < 32; rr += 4) {
            int row = m0 + rr;
            float4 v = (row < n) ? *(const float4*)&X[(size_t)row * FIN + kv]
                                 : make_float4(0.f, 0.f, 0.f, 0.f);
            *(float4*)&sX[rr][kv] = v;
        }
    }
    __syncthreads();

    const int tx = tid & 15, ty = tid >> 4;
    const int c0 = tx * 4, r0 = ty * 4;
    float acc[4][4] = {};
    #pragma unroll 8
    for (int k4 = 0; k4 < FIN; k4 += 4) {
        float4 xr[4];
        #pragma unroll
        for (int i = 0; i < 4; i++) xr[i] = *(const float4*)&sX[r0 + i][k4];
        #pragma unroll
        for (int kk = 0; kk < 4; kk++) {
            float4 wv = *(const float4*)&sW[k4 + kk][c0];
            #pragma unroll
            for (int i = 0; i < 4; i++) {
                float xs = ((const float*)&xr[i])[kk];
                acc[i][0] += xs * wv.x; acc[i][1] += xs * wv.y;
                acc[i][2] += xs * wv.z; acc[i][3] += xs * wv.w;
            }
        }
    }
    #pragma unroll
    for (int i = 0; i < 4; i++) {
        int row = m0 + r0 + i;
        if (row < n)
            *(float4*)&Y[(size_t)row * HD + c0] =
                make_float4(acc[i][0], acc[i][1], acc[i][2], acc[i][3]);
    }
}

// ---------------- GEMM2: Y[n,40] = X[n,64] @ W[64,40], 4x4 register tile ----------------
// BM=128 rows/block, 320 threads (10 tx x 32 ty), thread computes 4 rows x 4 cols.
__global__ __launch_bounds__(320)
void gemm2_kernel(const float* __restrict__ X, const float* __restrict__ W,
                  float* __restrict__ Y, int n) {
    __shared__ float sX[128][HD];    // 32KB
    __shared__ float sW[HD][CD];     // 10KB
    const int tid = threadIdx.x;
    const int m0  = blockIdx.x * 128;

    for (int i = tid; i < HD * CD / 4; i += 320)
        ((float4*)sW)[i] = ((const float4*)W)[i];
    for (int i = tid; i < 128 * (HD / 4); i += 320) {
        int rr = i >> 4;              // /16 float4s per row
        int kv = (i & 15) * 4;
        int row = m0 + rr;
        float4 v = (row < n) ? *(const float4*)&X[(size_t)row * HD + kv]
                             : make_float4(0.f, 0.f, 0.f, 0.f);
        *(float4*)&sX[rr][kv] = v;
    }
    __syncthreads();

    const int tx = tid % 10, ty = tid / 10;   // ty 0..31
    const int c0 = tx * 4, r0 = ty * 4;
    float acc[4][4] = {};
    #pragma unroll 4
    for (int k4 = 0; k4 < HD; k4 += 4) {
        float4 xr[4];
        #pragma unroll
        for (int i = 0; i < 4; i++) xr[i] = *(const float4*)&sX[r0 + i][k4];
        #pragma unroll
        for (int kk = 0; kk < 4; kk++) {
            float4 wv = *(const float4*)&sW[k4 + kk][c0];
            #pragma unroll
            for (int i = 0; i < 4; i++) {
                float xs = ((const float*)&xr[i])[kk];
                acc[i][0] += xs * wv.x; acc[i][1] += xs * wv.y;
                acc[i][2] += xs * wv.z; acc[i][3] += xs * wv.w;
            }
        }
    }
    #pragma unroll
    for (int i = 0; i < 4; i++) {
        int row = m0 + r0 + i;
        if (row < n)
            *(float4*)&Y[(size_t)row * CD + c0] =
                make_float4(acc[i][0], acc[i][1], acc[i][2], acc[i][3]);
    }
}

// ---------------- pull64 + relu + dropout epilogue: one warp per node ----------------
// out[node] = dropout(relu(bias + dinv^2*h[node] + sum_j ewgt[j]*dinv[node]*h[esrc[j]]))
__global__ __launch_bounds__(256)
void pull64_kernel(const int* __restrict__ rowptr, const int* __restrict__ esrc,
                   const float* __restrict__ ewgt, const float* __restrict__ dinv,
                   const float* __restrict__ h, const float* __restrict__ bias,
                   float* __restrict__ out, int n) {
    int wid  = (blockIdx.x * blockDim.x + threadIdx.x) >> 5;
    int lane = threadIdx.x & 31;
    if (wid >= n) return;
    const int node = wid;
    const int f = lane * 2;
    float wn = dinv[node];
    float2 acc = *(const float2*)&bias[f];
    float2 hv  = *(const float2*)&h[(size_t)node * HD + f];
    acc.x += wn * wn * hv.x;
    acc.y += wn * wn * hv.y;
    int s = rowptr[node], e = rowptr[node + 1];
    int j = s;
    for (; j + 2 <= e; j += 2) {
        int   s0 = esrc[j],     s1 = esrc[j + 1];
        float w0 = ewgt[j] * wn, w1 = ewgt[j + 1] * wn;
        float2 v0 = *(const float2*)&h[(size_t)s0 * HD + f];
        float2 v1 = *(const float2*)&h[(size_t)s1 * HD + f];
        acc.x += w0 * v0.x + w1 * v1.x;
        acc.y += w0 * v0.y + w1 * v1.y;
    }
    if (j < e) {
        int   s0 = esrc[j];
        float w0 = ewgt[j] * wn;
        float2 v0 = *(const float2*)&h[(size_t)s0 * HD + f];
        acc.x += w0 * v0.x;
        acc.y += w0 * v0.y;
    }
    // relu + deterministic dropout (JAX partitionable threefry, key 42)
    uint32_t i0 = (uint32_t)node * HD + (uint32_t)f;
    acc.x = dropout_scale_42(i0,      fmaxf(acc.x, 0.0f));
    acc.y = dropout_scale_42(i0 + 1u, fmaxf(acc.y, 0.0f));
    *(float2*)&out[(size_t)node * HD + f] = acc;
}

// ---------------- pull40 + log_softmax epilogue: one warp per node ----------------
__global__ __launch_bounds__(256)
void pull40_kernel(const int* __restrict__ rowptr, const int* __restrict__ esrc,
                   const float* __restrict__ ewgt, const float* __restrict__ dinv,
                   const float* __restrict__ h, const float* __restrict__ bias,
                   float* __restrict__ out, int n) {
    int wid  = (blockIdx.x * blockDim.x + threadIdx.x) >> 5;
    int lane = threadIdx.x & 31;
    if (wid >= n) return;
    const int node = wid;
    const bool act = lane < CD / 2;     // 20 active lanes, float2 each
    const int f = lane * 2;
    float wn = dinv[node];
    float2 acc = make_float2(0.f, 0.f);
    if (act) {
        acc = *(const float2*)&bias[f];
        float2 hv = *(const float2*)&h[(size_t)node * CD + f];
        acc.x += wn * wn * hv.x;
        acc.y += wn * wn * hv.y;
    }
    int s = rowptr[node], e = rowptr[node + 1];
    int j = s;
    for (; j + 2 <= e; j += 2) {
        int   s0 = esrc[j],      s1 = esrc[j + 1];
        float w0 = ewgt[j] * wn,  w1 = ewgt[j + 1] * wn;
        if (act) {
            float2 v0 = *(const float2*)&h[(size_t)s0 * CD + f];
            float2 v1 = *(const float2*)&h[(size_t)s1 * CD + f];
            acc.x += w0 * v0.x + w1 * v1.x;
            acc.y += w0 * v0.y + w1 * v1.y;
        }
    }
    if (j < e) {
        int   s0 = esrc[j];
        float w0 = ewgt[j] * wn;
        if (act) {
            float2 v0 = *(const float2*)&h[(size_t)s0 * CD + f];
            acc.x += w0 * v0.x;
            acc.y += w0 * v0.y;
        }
    }
    // log_softmax across the warp's 40 logits
    float m = act ? fmaxf(acc.x, acc.y) : -3.4e38f;
    #pragma unroll
    for (int o = 16; o; o >>= 1) m = fmaxf(m, __shfl_xor_sync(0xffffffffu, m, o));
    float sE = act ? (expf(acc.x - m) + expf(acc.y - m)) : 0.0f;
    #pragma unroll
    for (int o = 16; o; o >>= 1) sE += __shfl_xor_sync(0xffffffffu, sE, o);
    float ls = logf(sE);
    if (act)
        *(float2*)&out[(size_t)node * CD + f] = make_float2(acc.x - m - ls, acc.y - m - ls);
}

// ---------------- launch ----------------
extern "C" void kernel_launch(void* const* d_in, const int* in_sizes, int n_in,
                              void* d_out, int out_size) {
    const float* x  = (const float*)d_in[0];
    const int*   ei = (const int*)  d_in[1];
    const float* W1 = (const float*)d_in[2];
    const float* b1 = (const float*)d_in[3];
    const float* W2 = (const float*)d_in[4];
    const float* b2 = (const float*)d_in[5];
    float* out = (float*)d_out;

    const int n = NN;
    const int E = in_sizes[1] / 2;
    const int* row = ei;
    const int* col = ei + E;

    float *dinv, *h1, *agg1, *h2t, *ewgt;
    int *cnt, *rowptr, *cursor, *bsum, *esrc;
    cudaGetSymbolAddress((void**)&dinv,   g_dinv);
    cudaGetSymbolAddress((void**)&cnt,    g_cnt);
    cudaGetSymbolAddress((void**)&rowptr, g_rowptr);
    cudaGetSymbolAddress((void**)&cursor, g_cursor);
    cudaGetSymbolAddress((void**)&bsum,   g_bsum);
    cudaGetSymbolAddress((void**)&esrc,   g_esrc);
    cudaGetSymbolAddress((void**)&ewgt,   g_ewgt);
    cudaGetSymbolAddress((void**)&h1,     g_h1);
    cudaGetSymbolAddress((void**)&agg1,   g_agg1);
    cudaGetSymbolAddress((void**)&h2t,    g_h2t);

    const int T = 256;
    auto cdiv = [](long long a, long long b) { return (int)((a + b - 1) / b); };

    // ---- CSR build (also yields degree/dinv) ----
    cudaMemsetAsync(cnt, 0, NN * sizeof(int));
    hist_kernel <<<cdiv(E, T), T>>>(col, cnt, E);
    dinv_kernel <<<cdiv(n, T), T>>>(cnt, dinv, n);
    scan1_kernel<<<NB1, SCAN_BS>>>(cnt, rowptr, bsum, n);
    scan2_kernel<<<1, 256>>>(bsum, NB1);
    scan3_kernel<<<cdiv(n, T), T>>>(rowptr, cursor, bsum, n, E);
    fill_kernel <<<cdiv(E, T), T>>>(row, col, dinv, cursor, esrc, ewgt, E);

    // ---- layer 1: gemm + pull (+relu+dropout fused) ----
    gemm1_kernel<<<cdiv(n, 32), 128>>>(x, W1, h1, n);
    pull64_kernel<<<cdiv((long long)n * 32, T), T>>>(rowptr, esrc, ewgt, dinv, h1, b1, agg1, n);

    // ---- layer 2: gemm + pull (+log_softmax fused) straight into d_out ----
    gemm2_kernel<<<cdiv(n, 128), 320>>>(agg1, W2, h2t, n);
    pull40_kernel<<<cdiv((long long)n * 32, T), T>>>(rowptr, esrc, ewgt, dinv, h2t, b2, out, n);
}

// round 9
// speedup vs baseline: 2.3928x; 1.0580x over previous
#include <cuda_runtime.h>
#include <cuda_fp16.h>
#include <stdint.h>
#include <stddef.h>

#define NN    100000
#define EMAX  1600000
#define FIN   128
#define HD    64
#define CD    40

#define SCAN_BS   512
#define NB1       ((NN + SCAN_BS - 1) / SCAN_BS)   // 196

// ---------------- scratch (static device globals; no allocation) ----------------
__device__ float  g_dinv[NN];
__device__ int    g_cnt [NN];
__device__ int    g_rowptr[NN + 1];
__device__ int    g_cursor[NN];
__device__ int    g_bsum[NB1 + 1];
__device__ int2   g_epak[EMAX];                    // {src, bitcast(dinv[src])}
__device__ __half g_h1  [(size_t)NN * HD];         // gemm1 out (fp16, gathered by pull64)
__device__ float  g_agg1[(size_t)NN * HD];         // pull64+relu+dropout out (fp32, coalesced)
__device__ __half g_h2t [(size_t)NN * CD];         // gemm2 out (fp16, gathered by pull40)

// ---------------- threefry2x32 (bit-exact JAX partitionable path) ----------------
__device__ __forceinline__ uint32_t rotl32(uint32_t x, int d) {
    return __funnelshift_l(x, x, d);
}
__device__ __forceinline__ void tf_round(uint32_t& x0, uint32_t& x1, int r) {
    x0 += x1; x1 = rotl32(x1, r); x1 ^= x0;
}
__device__ __forceinline__ uint2 threefry_0_42(uint32_t x0, uint32_t x1) {
    const uint32_t k0 = 0u, k1 = 42u;
    const uint32_t k2 = 0u ^ 42u ^ 0x1BD11BDAu;
    x0 += k0; x1 += k1;
    tf_round(x0,x1,13); tf_round(x0,x1,15); tf_round(x0,x1,26); tf_round(x0,x1,6);
    x0 += k1; x1 += k2 + 1u;
    tf_round(x0,x1,17); tf_round(x0,x1,29); tf_round(x0,x1,16); tf_round(x0,x1,24);
    x0 += k2; x1 += k0 + 2u;
    tf_round(x0,x1,13); tf_round(x0,x1,15); tf_round(x0,x1,26); tf_round(x0,x1,6);
    x0 += k0; x1 += k1 + 3u;
    tf_round(x0,x1,17); tf_round(x0,x1,29); tf_round(x0,x1,16); tf_round(x0,x1,24);
    x0 += k1; x1 += k2 + 4u;
    tf_round(x0,x1,13); tf_round(x0,x1,15); tf_round(x0,x1,26); tf_round(x0,x1,6);
    x0 += k2; x1 += k0 + 5u;
    return make_uint2(x0, x1);
}
__device__ __forceinline__ float dropout_scale_42(uint32_t i, float v) {
    uint2 rnd = threefry_0_42(0u, i);
    uint32_t bits = rnd.x ^ rnd.y;
    float u = __uint_as_float((bits >> 9) | 0x3f800000u) - 1.0f;
    const float KEEP = (float)(1.0 - 0.4144);
    return (u < KEEP) ? (v / KEEP) : 0.0f;
}

// ---------------- CSR build ----------------
__global__ void hist_kernel(const int* __restrict__ col, int* __restrict__ cnt, int E) {
    int i = blockIdx.x * blockDim.x + threadIdx.x;
    if (i < E) atomicAdd(&cnt[col[i]], 1);
}
__global__ void dinv_kernel(const int* __restrict__ cnt, float* __restrict__ dinv, int n) {
    int i = blockIdx.x * blockDim.x + threadIdx.x;
    if (i < n) dinv[i] = (float)(1.0 / sqrt((double)(cnt[i] + 1)));   // +1 self loop
}
__global__ void scan1_kernel(const int* __restrict__ cnt, int* __restrict__ rowptr,
                             int* __restrict__ bsum, int n) {
    __shared__ int s[SCAN_BS];
    int tid = threadIdx.x;
    int gid = blockIdx.x * SCAN_BS + tid;
    int v = (gid < n) ? cnt[gid] : 0;
    s[tid] = v;
    __syncthreads();
    #pragma unroll
    for (int off = 1; off < SCAN_BS; off <<= 1) {
        int t = (tid >= off) ? s[tid - off] : 0;
        __syncthreads();
        s[tid] += t;
        __syncthreads();
    }
    if (gid < n) rowptr[gid] = s[tid] - v;
    if (tid == SCAN_BS - 1) bsum[blockIdx.x] = s[tid];
}
__global__ void scan2_kernel(int* __restrict__ bsum, int nb) {
    __shared__ int s[256];
    int tid = threadIdx.x;
    int v = (tid < nb) ? bsum[tid] : 0;
    s[tid] = v;
    __syncthreads();
    #pragma unroll
    for (int off = 1; off < 256; off <<= 1) {
        int t = (tid >= off) ? s[tid - off] : 0;
        __syncthreads();
        s[tid] += t;
        __syncthreads();
    }
    if (tid < nb) bsum[tid] = s[tid] - v;
}
__global__ void scan3_kernel(int* __restrict__ rowptr, int* __restrict__ cursor,
                             const int* __restrict__ bsum, int n, int E) {
    int i = blockIdx.x * blockDim.x + threadIdx.x;
    if (i < n) {
        int r = rowptr[i] + bsum[i / SCAN_BS];
        rowptr[i] = r;
        cursor[i] = r;
    }
    if (i == 0) rowptr[n] = E;
}
__global__ void fill_kernel(const int* __restrict__ row, const int* __restrict__ col,
                            const float* __restrict__ dinv,
                            int* __restrict__ cursor, int2* __restrict__ epak, int E) {
    int e = blockIdx.x * blockDim.x + threadIdx.x;
    if (e >= E) return;
    int r = row[e], c = col[e];
    int pos = atomicAdd(&cursor[c], 1);
    epak[pos] = make_int2(r, __float_as_int(dinv[r]));
}

// ---------------- GEMM1: h1[n,64](fp16) = X[n,128] @ W1[128,64], 4x4 register tile ----------------
__global__ __launch_bounds__(128)
void gemm1_kernel(const float* __restrict__ X, const float* __restrict__ W,
                  __half* __restrict__ Y, int n) {
    __shared__ float sX[32][FIN];    // 16KB
    __shared__ float sW[FIN][HD];    // 32KB
    const int tid = threadIdx.x;
    const int m0  = blockIdx.x * 32;

    for (int i = tid; i < FIN * HD / 4; i += 128)
        ((float4*)sW)[i] = ((const float4*)W)[i];
    {
        int r  = tid >> 5;
        int kv = (tid & 31) * 4;
        #pragma unroll
        for (int rr = r; rr < 32; rr += 4) {
            int row = m0 + rr;
            float4 v = (row < n) ? *(const float4*)&X[(size_t)row * FIN + kv]
                                 : make_float4(0.f, 0.f, 0.f, 0.f);
            *(float4*)&sX[rr][kv] = v;
        }
    }
    __syncthreads();

    const int tx = tid & 15, ty = tid >> 4;
    const int c0 = tx * 4, r0 = ty * 4;
    float acc[4][4] = {};
    #pragma unroll 8
    for (int k4 = 0; k4 < FIN; k4 += 4) {
        float4 xr[4];
        #pragma unroll
        for (int i = 0; i < 4; i++) xr[i] = *(const float4*)&sX[r0 + i][k4];
        #pragma unroll
        for (int kk = 0; kk < 4; kk++) {
            float4 wv = *(const float4*)&sW[k4 + kk][c0];
            #pragma unroll
            for (int i = 0; i < 4; i++) {
                float xs = ((const float*)&xr[i])[kk];
                acc[i][0] += xs * wv.x; acc[i][1] += xs * wv.y;
                acc[i][2] += xs * wv.z; acc[i][3] += xs * wv.w;
            }
        }
    }
    #pragma unroll
    for (int i = 0; i < 4; i++) {
        int row = m0 + r0 + i;
        if (row < n) {
            __half2 p0 = __floats2half2_rn(acc[i][0], acc[i][1]);
            __half2 p1 = __floats2half2_rn(acc[i][2], acc[i][3]);
            uint2 u = make_uint2(*(uint32_t*)&p0, *(uint32_t*)&p1);
            *(uint2*)&Y[(size_t)row * HD + c0] = u;
        }
    }
}

// ---------------- GEMM2: h2t[n,40](fp16) = agg1[n,64](fp32) @ W2[64,40] ----------------
__global__ __launch_bounds__(320)
void gemm2_kernel(const float* __restrict__ X, const float* __restrict__ W,
                  __half* __restrict__ Y, int n) {
    __shared__ float sX[128][HD];    // 32KB
    __shared__ float sW[HD][CD];     // 10KB
    const int tid = threadIdx.x;
    const int m0  = blockIdx.x * 128;

    for (int i = tid; i < HD * CD / 4; i += 320)
        ((float4*)sW)[i] = ((const float4*)W)[i];
    for (int i = tid; i < 128 * (HD / 4); i += 320) {
        int rr = i >> 4;
        int kv = (i & 15) * 4;
        int row = m0 + rr;
        float4 v = (row < n) ? *(const float4*)&X[(size_t)row * HD + kv]
                             : make_float4(0.f, 0.f, 0.f, 0.f);
        *(float4*)&sX[rr][kv] = v;
    }
    __syncthreads();

    const int tx = tid % 10, ty = tid / 10;
    const int c0 = tx * 4, r0 = ty * 4;
    float acc[4][4] = {};
    #pragma unroll 4
    for (int k4 = 0; k4 < HD; k4 += 4) {
        float4 xr[4];
        #pragma unroll
        for (int i = 0; i < 4; i++) xr[i] = *(const float4*)&sX[r0 + i][k4];
        #pragma unroll
        for (int kk = 0; kk < 4; kk++) {
            float4 wv = *(const float4*)&sW[k4 + kk][c0];
            #pragma unroll
            for (int i = 0; i < 4; i++) {
                float xs = ((const float*)&xr[i])[kk];
                acc[i][0] += xs * wv.x; acc[i][1] += xs * wv.y;
                acc[i][2] += xs * wv.z; acc[i][3] += xs * wv.w;
            }
        }
    }
    #pragma unroll
    for (int i = 0; i < 4; i++) {
        int row = m0 + r0 + i;
        if (row < n) {
            __half2 p0 = __floats2half2_rn(acc[i][0], acc[i][1]);
            __half2 p1 = __floats2half2_rn(acc[i][2], acc[i][3]);
            uint2 u = make_uint2(*(uint32_t*)&p0, *(uint32_t*)&p1);
            *(uint2*)&Y[(size_t)row * CD + c0] = u;
        }
    }
}

// ---------------- pull64 (fp16 gather) + relu + dropout epilogue ----------------
__global__ __launch_bounds__(256)
void pull64_kernel(const int* __restrict__ rowptr, const int2* __restrict__ epak,
                   const float* __restrict__ dinv, const __half* __restrict__ h,
                   const float* __restrict__ bias, float* __restrict__ out, int n) {
    int wid  = (blockIdx.x * blockDim.x + threadIdx.x) >> 5;
    int lane = threadIdx.x & 31;
    if (wid >= n) return;
    const int node = wid;
    const __half2* hh = (const __half2*)h;         // HD/2 = 32 half2 per row
    float wn = dinv[node];
    float2 acc = *(const float2*)&bias[lane * 2];
    {
        float2 hv = __half22float2(hh[(size_t)node * 32 + lane]);
        acc.x += wn * wn * hv.x;
        acc.y += wn * wn * hv.y;
    }
    int s = rowptr[node], e = rowptr[node + 1];
    int j = s;
    for (; j + 2 <= e; j += 2) {
        int2 p0 = epak[j], p1 = epak[j + 1];
        float w0 = __int_as_float(p0.y) * wn, w1 = __int_as_float(p1.y) * wn;
        float2 v0 = __half22float2(hh[(size_t)p0.x * 32 + lane]);
        float2 v1 = __half22float2(hh[(size_t)p1.x * 32 + lane]);
        acc.x += w0 * v0.x + w1 * v1.x;
        acc.y += w0 * v0.y + w1 * v1.y;
    }
    if (j < e) {
        int2 p0 = epak[j];
        float w0 = __int_as_float(p0.y) * wn;
        float2 v0 = __half22float2(hh[(size_t)p0.x * 32 + lane]);
        acc.x += w0 * v0.x;
        acc.y += w0 * v0.y;
    }
    uint32_t i0 = (uint32_t)node * HD + (uint32_t)(lane * 2);
    acc.x = dropout_scale_42(i0,      fmaxf(acc.x, 0.0f));
    acc.y = dropout_scale_42(i0 + 1u, fmaxf(acc.y, 0.0f));
    *(float2*)&out[(size_t)node * HD + lane * 2] = acc;
}

// ---------------- pull40 (fp16 gather) + log_softmax epilogue ----------------
__global__ __launch_bounds__(256)
void pull40_kernel(const int* __restrict__ rowptr, const int2* __restrict__ epak,
                   const float* __restrict__ dinv, const __half* __restrict__ h,
                   const float* __restrict__ bias, float* __restrict__ out, int n) {
    int wid  = (blockIdx.x * blockDim.x + threadIdx.x) >> 5;
    int lane = threadIdx.x & 31;
    if (wid >= n) return;
    const int node = wid;
    const bool act = lane < CD / 2;                // 20 active lanes
    const __half2* hh = (const __half2*)h;         // CD/2 = 20 half2 per row
    float wn = dinv[node];
    float2 acc = make_float2(0.f, 0.f);
    if (act) {
        acc = *(const float2*)&bias[lane * 2];
        float2 hv = __half22float2(hh[(size_t)node * 20 + lane]);
        acc.x += wn * wn * hv.x;
        acc.y += wn * wn * hv.y;
    }
    int s = rowptr[node], e = rowptr[node + 1];
    int j = s;
    for (; j + 2 <= e; j += 2) {
        int2 p0 = epak[j], p1 = epak[j + 1];
        float w0 = __int_as_float(p0.y) * wn, w1 = __int_as_float(p1.y) * wn;
        if (act) {
            float2 v0 = __half22float2(hh[(size_t)p0.x * 20 + lane]);
            float2 v1 = __half22float2(hh[(size_t)p1.x * 20 + lane]);
            acc.x += w0 * v0.x + w1 * v1.x;
            acc.y += w0 * v0.y + w1 * v1.y;
        }
    }
    if (j < e) {
        int2 p0 = epak[j];
        float w0 = __int_as_float(p0.y) * wn;
        if (act) {
            float2 v0 = __half22float2(hh[(size_t)p0.x * 20 + lane]);
            acc.x += w0 * v0.x;
            acc.y += w0 * v0.y;
        }
    }
    float m = act ? fmaxf(acc.x, acc.y) : -3.4e38f;
    #pragma unroll
    for (int o = 16; o; o >>= 1) m = fmaxf(m, __shfl_xor_sync(0xffffffffu, m, o));
    float sE = act ? (expf(acc.x - m) + expf(acc.y - m)) : 0.0f;
    #pragma unroll
    for (int o = 16; o; o >>= 1) sE += __shfl_xor_sync(0xffffffffu, sE, o);
    float ls = logf(sE);
    if (act)
        *(float2*)&out[(size_t)node * CD + lane * 2] =
            make_float2(acc.x - m - ls, acc.y - m - ls);
}

// ---------------- launch ----------------
extern "C" void kernel_launch(void* const* d_in, const int* in_sizes, int n_in,
                              void* d_out, int out_size) {
    const float* x  = (const float*)d_in[0];
    const int*   ei = (const int*)  d_in[1];
    const float* W1 = (const float*)d_in[2];
    const float* b1 = (const float*)d_in[3];
    const float* W2 = (const float*)d_in[4];
    const float* b2 = (const float*)d_in[5];
    float* out = (float*)d_out;

    const int n = NN;
    const int E = in_sizes[1] / 2;
    const int* row = ei;
    const int* col = ei + E;

    float *dinv, *agg1;
    __half *h1, *h2t;
    int *cnt, *rowptr, *cursor, *bsum;
    int2 *epak;
    cudaGetSymbolAddress((void**)&dinv,   g_dinv);
    cudaGetSymbolAddress((void**)&cnt,    g_cnt);
    cudaGetSymbolAddress((void**)&rowptr, g_rowptr);
    cudaGetSymbolAddress((void**)&cursor, g_cursor);
    cudaGetSymbolAddress((void**)&bsum,   g_bsum);
    cudaGetSymbolAddress((void**)&epak,   g_epak);
    cudaGetSymbolAddress((void**)&h1,     g_h1);
    cudaGetSymbolAddress((void**)&agg1,   g_agg1);
    cudaGetSymbolAddress((void**)&h2t,    g_h2t);

    // side stream + fork/join events, created once (first call is the uncaptured
    // correctness run; subsequent captures reuse them)
    static cudaStream_t s_csr = 0;
    static cudaEvent_t  e_fork = 0, e_join = 0;
    if (!s_csr) {
        cudaStreamCreateWithFlags(&s_csr, cudaStreamNonBlocking);
        cudaEventCreateWithFlags(&e_fork, cudaEventDisableTiming);
        cudaEventCreateWithFlags(&e_join, cudaEventDisableTiming);
    }

    const int T = 256;
    auto cdiv = [](long long a, long long b) { return (int)((a + b - 1) / b); };

    // ---- fork: CSR build on side stream, gemm1 on main stream ----
    cudaEventRecord(e_fork, 0);
    cudaStreamWaitEvent(s_csr, e_fork, 0);

    cudaMemsetAsync(cnt, 0, NN * sizeof(int), s_csr);
    hist_kernel <<<cdiv(E, T), T, 0, s_csr>>>(col, cnt, E);
    dinv_kernel <<<cdiv(n, T), T, 0, s_csr>>>(cnt, dinv, n);
    scan1_kernel<<<NB1, SCAN_BS, 0, s_csr>>>(cnt, rowptr, bsum, n);
    scan2_kernel<<<1, 256, 0, s_csr>>>(bsum, NB1);
    scan3_kernel<<<cdiv(n, T), T, 0, s_csr>>>(rowptr, cursor, bsum, n, E);
    fill_kernel <<<cdiv(E, T), T, 0, s_csr>>>(row, col, dinv, cursor, epak, E);
    cudaEventRecord(e_join, s_csr);

    gemm1_kernel<<<cdiv(n, 32), 128>>>(x, W1, h1, n);

    // ---- join, then the dependent chain on the main stream ----
    cudaStreamWaitEvent(0, e_join, 0);
    pull64_kernel<<<cdiv((long long)n * 32, T), T>>>(rowptr, epak, dinv, h1, b1, agg1, n);
    gemm2_kernel<<<cdiv(n, 128), 320>>>(agg1, W2, h2t, n);
    pull40_kernel<<<cdiv((long long)n * 32, T), T>>>(rowptr, epak, dinv, h2t, b2, out, n);
}

// round 11
// speedup vs baseline: 2.4969x; 1.0435x over previous
#include <cuda_runtime.h>
#include <cuda_fp16.h>
#include <stdint.h>
#include <stddef.h>

#define NN    100000
#define EMAX  1600000
#define FIN   128
#define HD    64
#define CD    40

#define SCAN_BS   512
#define NB1       ((NN + SCAN_BS - 1) / SCAN_BS)   // 196
#define NMASKW    ((NN * HD) / 32)                  // 200,000 packed mask words

#define GEMM1_SMEM ((64 * FIN + FIN * HD) * (int)sizeof(float))   // 64KB

// ---------------- scratch (static device globals; no allocation) ----------------
__device__ float    g_dinv[NN];
__device__ int      g_cnt [NN];
__device__ int      g_rowptr[NN + 1];
__device__ int      g_cursor[NN];
__device__ int      g_bsum[NB1 + 1];
__device__ int2     g_epak[EMAX];                  // {src, bitcast(dinv[src])}
__device__ uint32_t g_mask[NMASKW];                // packed dropout keep-bits
__device__ __half   g_h1  [(size_t)NN * HD];       // gemm1 out (fp16, gathered by pull64)
__device__ float    g_agg1[(size_t)NN * HD];       // pull64+relu+dropout out (fp32)
__device__ __half   g_h2t [(size_t)NN * CD];       // gemm2 out (fp16, gathered by pull40)

// ---------------- threefry2x32 (bit-exact JAX partitionable path) ----------------
__device__ __forceinline__ uint32_t rotl32(uint32_t x, int d) {
    return __funnelshift_l(x, x, d);
}
__device__ __forceinline__ void tf_round(uint32_t& x0, uint32_t& x1, int r) {
    x0 += x1; x1 = rotl32(x1, r); x1 ^= x0;
}
__device__ __forceinline__ uint2 threefry_0_42(uint32_t x0, uint32_t x1) {
    const uint32_t k0 = 0u, k1 = 42u;
    const uint32_t k2 = 0u ^ 42u ^ 0x1BD11BDAu;
    x0 += k0; x1 += k1;
    tf_round(x0,x1,13); tf_round(x0,x1,15); tf_round(x0,x1,26); tf_round(x0,x1,6);
    x0 += k1; x1 += k2 + 1u;
    tf_round(x0,x1,17); tf_round(x0,x1,29); tf_round(x0,x1,16); tf_round(x0,x1,24);
    x0 += k2; x1 += k0 + 2u;
    tf_round(x0,x1,13); tf_round(x0,x1,15); tf_round(x0,x1,26); tf_round(x0,x1,6);
    x0 += k0; x1 += k1 + 3u;
    tf_round(x0,x1,17); tf_round(x0,x1,29); tf_round(x0,x1,16); tf_round(x0,x1,24);
    x0 += k1; x1 += k2 + 4u;
    tf_round(x0,x1,13); tf_round(x0,x1,15); tf_round(x0,x1,26); tf_round(x0,x1,6);
    x0 += k2; x1 += k0 + 5u;
    return make_uint2(x0, x1);
}

// ---------------- dropout mask precompute: 8 elements per thread ----------------
__global__ void mask_kernel(uint32_t* __restrict__ mask, int nwords) {
    int t = blockIdx.x * blockDim.x + threadIdx.x;   // one byte (8 bits) per thread
    int nq = nwords * 4;
    if (t >= nq) return;
    const float KEEP = (float)(1.0 - 0.4144);
    uint32_t base = (uint32_t)t * 8u;
    uint32_t byte = 0;
    #pragma unroll
    for (int b = 0; b < 8; b++) {
        uint2 rnd = threefry_0_42(0u, base + (uint32_t)b);
        uint32_t bits = rnd.x ^ rnd.y;
        float u = __uint_as_float((bits >> 9) | 0x3f800000u) - 1.0f;
        byte |= (u < KEEP ? 1u : 0u) << b;
    }
    ((uint8_t*)mask)[t] = (uint8_t)byte;
}

// ---------------- CSR build ----------------
__global__ void hist_kernel(const int* __restrict__ col, int* __restrict__ cnt, int E) {
    int i = blockIdx.x * blockDim.x + threadIdx.x;
    if (i < E) atomicAdd(&cnt[col[i]], 1);
}
__global__ void dinv_kernel(const int* __restrict__ cnt, float* __restrict__ dinv, int n) {
    int i = blockIdx.x * blockDim.x + threadIdx.x;
    if (i < n) dinv[i] = (float)(1.0 / sqrt((double)(cnt[i] + 1)));   // +1 self loop
}
__global__ void scan1_kernel(const int* __restrict__ cnt, int* __restrict__ rowptr,
                             int* __restrict__ bsum, int n) {
    __shared__ int s[SCAN_BS];
    int tid = threadIdx.x;
    int gid = blockIdx.x * SCAN_BS + tid;
    int v = (gid < n) ? cnt[gid] : 0;
    s[tid] = v;
    __syncthreads();
    #pragma unroll
    for (int off = 1; off < SCAN_BS; off <<= 1) {
        int t = (tid >= off) ? s[tid - off] : 0;
        __syncthreads();
        s[tid] += t;
        __syncthreads();
    }
    if (gid < n) rowptr[gid] = s[tid] - v;
    if (tid == SCAN_BS - 1) bsum[blockIdx.x] = s[tid];
}
__global__ void scan2_kernel(int* __restrict__ bsum, int nb) {
    __shared__ int s[256];
    int tid = threadIdx.x;
    int v = (tid < nb) ? bsum[tid] : 0;
    s[tid] = v;
    __syncthreads();
    #pragma unroll
    for (int off = 1; off < 256; off <<= 1) {
        int t = (tid >= off) ? s[tid - off] : 0;
        __syncthreads();
        s[tid] += t;
        __syncthreads();
    }
    if (tid < nb) bsum[tid] = s[tid] - v;
}
__global__ void scan3_kernel(int* __restrict__ rowptr, int* __restrict__ cursor,
                             const int* __restrict__ bsum, int n, int E) {
    int i = blockIdx.x * blockDim.x + threadIdx.x;
    if (i < n) {
        int r = rowptr[i] + bsum[i / SCAN_BS];
        rowptr[i] = r;
        cursor[i] = r;
    }
    if (i == 0) rowptr[n] = E;
}
__global__ void fill_kernel(const int* __restrict__ row, const int* __restrict__ col,
                            const float* __restrict__ dinv,
                            int* __restrict__ cursor, int2* __restrict__ epak, int E) {
    int e = blockIdx.x * blockDim.x + threadIdx.x;
    if (e >= E) return;
    int r = row[e], c = col[e];
    int pos = atomicAdd(&cursor[c], 1);
    epak[pos] = make_int2(r, __float_as_int(dinv[r]));
}

// ---------------- GEMM1: h1[n,64](fp16) = X[n,128] @ W1[128,64] ----------------
// BM=64 rows/block, 256 threads (16 tx x 16 ty), 4x4 register tile.
// 64KB DYNAMIC smem: sX[64][128] then sW[128][64].
__global__ __launch_bounds__(256)
void gemm1_kernel(const float* __restrict__ X, const float* __restrict__ W,
                  __half* __restrict__ Y, int n) {
    extern __shared__ float smem[];
    float (*sX)[FIN] = (float(*)[FIN])smem;              // 32KB
    float (*sW)[HD]  = (float(*)[HD])(smem + 64 * FIN);  // 32KB
    const int tid = threadIdx.x;
    const int m0  = blockIdx.x * 64;

    for (int i = tid; i < FIN * HD / 4; i += 256)
        ((float4*)sW)[i] = ((const float4*)W)[i];
    for (int i = tid; i < 64 * (FIN / 4); i += 256) {
        int rr = i >> 5;              // /32 float4s per row
        int kv = (i & 31) * 4;
        int row = m0 + rr;
        float4 v = (row < n) ? *(const float4*)&X[(size_t)row * FIN + kv]
                             : make_float4(0.f, 0.f, 0.f, 0.f);
        *(float4*)&sX[rr][kv] = v;
    }
    __syncthreads();

    const int tx = tid & 15, ty = tid >> 4;
    const int c0 = tx * 4, r0 = ty * 4;
    float acc[4][4] = {};
    #pragma unroll 8
    for (int k4 = 0; k4 < FIN; k4 += 4) {
        float4 xr[4];
        #pragma unroll
        for (int i = 0; i < 4; i++) xr[i] = *(const float4*)&sX[r0 + i][k4];
        #pragma unroll
        for (int kk = 0; kk < 4; kk++) {
            float4 wv = *(const float4*)&sW[k4 + kk][c0];
            #pragma unroll
            for (int i = 0; i < 4; i++) {
                float xs = ((const float*)&xr[i])[kk];
                acc[i][0] += xs * wv.x; acc[i][1] += xs * wv.y;
                acc[i][2] += xs * wv.z; acc[i][3] += xs * wv.w;
            }
        }
    }
    #pragma unroll
    for (int i = 0; i < 4; i++) {
        int row = m0 + r0 + i;
        if (row < n) {
            __half2 p0 = __floats2half2_rn(acc[i][0], acc[i][1]);
            __half2 p1 = __floats2half2_rn(acc[i][2], acc[i][3]);
            uint2 u = make_uint2(*(uint32_t*)&p0, *(uint32_t*)&p1);
            *(uint2*)&Y[(size_t)row * HD + c0] = u;
        }
    }
}

// ---------------- GEMM2: h2t[n,40](fp16) = agg1[n,64](fp32) @ W2[64,40] ----------------
__global__ __launch_bounds__(320)
void gemm2_kernel(const float* __restrict__ X, const float* __restrict__ W,
                  __half* __restrict__ Y, int n) {
    __shared__ float sX[128][HD];    // 32KB
    __shared__ float sW[HD][CD];     // 10KB
    const int tid = threadIdx.x;
    const int m0  = blockIdx.x * 128;

    for (int i = tid; i < HD * CD / 4; i += 320)
        ((float4*)sW)[i] = ((const float4*)W)[i];
    for (int i = tid; i < 128 * (HD / 4); i += 320) {
        int rr = i >> 4;
        int kv = (i & 15) * 4;
        int row = m0 + rr;
        float4 v = (row < n) ? *(const float4*)&X[(size_t)row * HD + kv]
                             : make_float4(0.f, 0.f, 0.f, 0.f);
        *(float4*)&sX[rr][kv] = v;
    }
    __syncthreads();

    const int tx = tid % 10, ty = tid / 10;
    const int c0 = tx * 4, r0 = ty * 4;
    float acc[4][4] = {};
    #pragma unroll 4
    for (int k4 = 0; k4 < HD; k4 += 4) {
        float4 xr[4];
        #pragma unroll
        for (int i = 0; i < 4; i++) xr[i] = *(const float4*)&sX[r0 + i][k4];
        #pragma unroll
        for (int kk = 0; kk < 4; kk++) {
            float4 wv = *(const float4*)&sW[k4 + kk][c0];
            #pragma unroll
            for (int i = 0; i < 4; i++) {
                float xs = ((const float*)&xr[i])[kk];
                acc[i][0] += xs * wv.x; acc[i][1] += xs * wv.y;
                acc[i][2] += xs * wv.z; acc[i][3] += xs * wv.w;
            }
        }
    }
    #pragma unroll
    for (int i = 0; i < 4; i++) {
        int row = m0 + r0 + i;
        if (row < n) {
            __half2 p0 = __floats2half2_rn(acc[i][0], acc[i][1]);
            __half2 p1 = __floats2half2_rn(acc[i][2], acc[i][3]);
            uint2 u = make_uint2(*(uint32_t*)&p0, *(uint32_t*)&p1);
            *(uint2*)&Y[(size_t)row * CD + c0] = u;
        }
    }
}

// ---------------- pull64 (fp16 gather) + relu + precomputed-mask dropout ----------------
__global__ __launch_bounds__(256)
void pull64_kernel(const int* __restrict__ rowptr, const int2* __restrict__ epak,
                   const float* __restrict__ dinv, const __half* __restrict__ h,
                   const float* __restrict__ bias, const uint32_t* __restrict__ mask,
                   float* __restrict__ out, int n) {
    int wid  = (blockIdx.x * blockDim.x + threadIdx.x) >> 5;
    int lane = threadIdx.x & 31;
    if (wid >= n) return;
    const int node = wid;
    const __half2* hh = (const __half2*)h;         // 32 half2 per row
    float wn = dinv[node];
    float2 acc = *(const float2*)&bias[lane * 2];
    {
        float2 hv = __half22float2(hh[(size_t)node * 32 + lane]);
        acc.x += wn * wn * hv.x;
        acc.y += wn * wn * hv.y;
    }
    int s = rowptr[node], e = rowptr[node + 1];
    int j = s;
    for (; j + 4 <= e; j += 4) {
        int2 p0 = epak[j],     p1 = epak[j + 1];
        int2 p2 = epak[j + 2], p3 = epak[j + 3];
        float2 v0 = __half22float2(hh[(size_t)p0.x * 32 + lane]);
        float2 v1 = __half22float2(hh[(size_t)p1.x * 32 + lane]);
        float2 v2 = __half22float2(hh[(size_t)p2.x * 32 + lane]);
        float2 v3 = __half22float2(hh[(size_t)p3.x * 32 + lane]);
        float w0 = __int_as_float(p0.y) * wn, w1 = __int_as_float(p1.y) * wn;
        float w2 = __int_as_float(p2.y) * wn, w3 = __int_as_float(p3.y) * wn;
        acc.x += w0 * v0.x + w1 * v1.x + w2 * v2.x + w3 * v3.x;
        acc.y += w0 * v0.y + w1 * v1.y + w2 * v2.y + w3 * v3.y;
    }
    for (; j < e; j++) {
        int2 p0 = epak[j];
        float w0 = __int_as_float(p0.y) * wn;
        float2 v0 = __half22float2(hh[(size_t)p0.x * 32 + lane]);
        acc.x += w0 * v0.x;
        acc.y += w0 * v0.y;
    }
    // relu + dropout via precomputed bit mask
    const float KEEP = (float)(1.0 - 0.4144);
    uint32_t wbits = mask[node * 2 + (lane >> 4)];
    int b = (lane * 2) & 31;
    acc.x = (wbits >> b)       & 1u ? fmaxf(acc.x, 0.0f) / KEEP : 0.0f;
    acc.y = (wbits >> (b + 1)) & 1u ? fmaxf(acc.y, 0.0f) / KEEP : 0.0f;
    *(float2*)&out[(size_t)node * HD + lane * 2] = acc;
}

// ---------------- pull40 (fp16 gather) + log_softmax epilogue ----------------
__global__ __launch_bounds__(256)
void pull40_kernel(const int* __restrict__ rowptr, const int2* __restrict__ epak,
                   const float* __restrict__ dinv, const __half* __restrict__ h,
                   const float* __restrict__ bias, float* __restrict__ out, int n) {
    int wid  = (blockIdx.x * blockDim.x + threadIdx.x) >> 5;
    int lane = threadIdx.x & 31;
    if (wid >= n) return;
    const int node = wid;
    const bool act = lane < CD / 2;                // 20 active lanes
    const __half2* hh = (const __half2*)h;         // 20 half2 per row
    float wn = dinv[node];
    float2 acc = make_float2(0.f, 0.f);
    if (act) {
        acc = *(const float2*)&bias[lane * 2];
        float2 hv = __half22float2(hh[(size_t)node * 20 + lane]);
        acc.x += wn * wn * hv.x;
        acc.y += wn * wn * hv.y;
    }
    int s = rowptr[node], e = rowptr[node + 1];
    int j = s;
    for (; j + 4 <= e; j += 4) {
        int2 p0 = epak[j],     p1 = epak[j + 1];
        int2 p2 = epak[j + 2], p3 = epak[j + 3];
        if (act) {
            float2 v0 = __half22float2(hh[(size_t)p0.x * 20 + lane]);
            float2 v1 = __half22float2(hh[(size_t)p1.x * 20 + lane]);
            float2 v2 = __half22float2(hh[(size_t)p2.x * 20 + lane]);
            float2 v3 = __half22float2(hh[(size_t)p3.x * 20 + lane]);
            float w0 = __int_as_float(p0.y) * wn, w1 = __int_as_float(p1.y) * wn;
            float w2 = __int_as_float(p2.y) * wn, w3 = __int_as_float(p3.y) * wn;
            acc.x += w0 * v0.x + w1 * v1.x + w2 * v2.x + w3 * v3.x;
            acc.y += w0 * v0.y + w1 * v1.y + w2 * v2.y + w3 * v3.y;
        }
    }
    for (; j < e; j++) {
        int2 p0 = epak[j];
        float w0 = __int_as_float(p0.y) * wn;
        if (act) {
            float2 v0 = __half22float2(hh[(size_t)p0.x * 20 + lane]);
            acc.x += w0 * v0.x;
            acc.y += w0 * v0.y;
        }
    }
    float m = act ? fmaxf(acc.x, acc.y) : -3.4e38f;
    #pragma unroll
    for (int o = 16; o; o >>= 1) m = fmaxf(m, __shfl_xor_sync(0xffffffffu, m, o));
    float sE = act ? (expf(acc.x - m) + expf(acc.y - m)) : 0.0f;
    #pragma unroll
    for (int o = 16; o; o >>= 1) sE += __shfl_xor_sync(0xffffffffu, sE, o);
    float ls = logf(sE);
    if (act)
        *(float2*)&out[(size_t)node * CD + lane * 2] =
            make_float2(acc.x - m - ls, acc.y - m - ls);
}

// ---------------- launch ----------------
extern "C" void kernel_launch(void* const* d_in, const int* in_sizes, int n_in,
                              void* d_out, int out_size) {
    const float* x  = (const float*)d_in[0];
    const int*   ei = (const int*)  d_in[1];
    const float* W1 = (const float*)d_in[2];
    const float* b1 = (const float*)d_in[3];
    const float* W2 = (const float*)d_in[4];
    const float* b2 = (const float*)d_in[5];
    float* out = (float*)d_out;

    const int n = NN;
    const int E = in_sizes[1] / 2;
    const int* row = ei;
    const int* col = ei + E;

    float *dinv, *agg1;
    __half *h1, *h2t;
    int *cnt, *rowptr, *cursor, *bsum;
    int2 *epak;
    uint32_t *mask;
    cudaGetSymbolAddress((void**)&dinv,   g_dinv);
    cudaGetSymbolAddress((void**)&cnt,    g_cnt);
    cudaGetSymbolAddress((void**)&rowptr, g_rowptr);
    cudaGetSymbolAddress((void**)&cursor, g_cursor);
    cudaGetSymbolAddress((void**)&bsum,   g_bsum);
    cudaGetSymbolAddress((void**)&epak,   g_epak);
    cudaGetSymbolAddress((void**)&mask,   g_mask);
    cudaGetSymbolAddress((void**)&h1,     g_h1);
    cudaGetSymbolAddress((void**)&agg1,   g_agg1);
    cudaGetSymbolAddress((void**)&h2t,    g_h2t);

    static cudaStream_t s_csr = 0;
    static cudaEvent_t  e_fork = 0, e_join = 0;
    if (!s_csr) {
        cudaStreamCreateWithFlags(&s_csr, cudaStreamNonBlocking);
        cudaEventCreateWithFlags(&e_fork, cudaEventDisableTiming);
        cudaEventCreateWithFlags(&e_join, cudaEventDisableTiming);
        cudaFuncSetAttribute(gemm1_kernel,
                             cudaFuncAttributeMaxDynamicSharedMemorySize, GEMM1_SMEM);
    }

    const int T = 256;
    auto cdiv = [](long long a, long long b) { return (int)((a + b - 1) / b); };

    // ---- fork: CSR build + dropout mask on side stream, gemm1 on main stream ----
    cudaEventRecord(e_fork, 0);
    cudaStreamWaitEvent(s_csr, e_fork, 0);

    cudaMemsetAsync(cnt, 0, NN * sizeof(int), s_csr);
    hist_kernel <<<cdiv(E, T), T, 0, s_csr>>>(col, cnt, E);
    dinv_kernel <<<cdiv(n, T), T, 0, s_csr>>>(cnt, dinv, n);
    scan1_kernel<<<NB1, SCAN_BS, 0, s_csr>>>(cnt, rowptr, bsum, n);
    scan2_kernel<<<1, 256, 0, s_csr>>>(bsum, NB1);
    scan3_kernel<<<cdiv(n, T), T, 0, s_csr>>>(rowptr, cursor, bsum, n, E);
    fill_kernel <<<cdiv(E, T), T, 0, s_csr>>>(row, col, dinv, cursor, epak, E);
    mask_kernel <<<cdiv((long long)NMASKW * 4, T), T, 0, s_csr>>>(mask, NMASKW);
    cudaEventRecord(e_join, s_csr);

    gemm1_kernel<<<cdiv(n, 64), 256, GEMM1_SMEM>>>(x, W1, h1, n);

    // ---- join, then the dependent chain on the main stream ----
    cudaStreamWaitEvent(0, e_join, 0);
    pull64_kernel<<<cdiv((long long)n * 32, T), T>>>(rowptr, epak, dinv, h1, b1, mask, agg1, n);
    gemm2_kernel<<<cdiv(n, 128), 320>>>(agg1, W2, h2t, n);
    pull40_kernel<<<cdiv((long long)n * 32, T), T>>>(rowptr, epak, dinv, h2t, b2, out, n);
}

// round 12
// speedup vs baseline: 2.5405x; 1.0174x over previous
#include <cuda_runtime.h>
#include <cuda_fp16.h>
#include <stdint.h>
#include <stddef.h>

#define NN    100000
#define EMAX  1600000
#define FIN   128
#define HD    64
#define CD    40

#define SCAN_BS   512
#define NB1       ((NN + SCAN_BS - 1) / SCAN_BS)   // 196
#define NMASKW    ((NN * HD) / 32)                  // 200,000 packed mask words
#define NMASKB    (NN * HD / 8)                     // 800,000 mask bytes

#define GEMM1_SMEM ((64 * FIN + FIN * HD) * (int)sizeof(float))   // 64KB

#define FLAG_A 1ULL
#define FLAG_P 2ULL

// ---------------- scratch (static device globals; no allocation) ----------------
__device__ float    g_dinv[NN];
__device__ int      g_cnt [NN];
__device__ int      g_rowptr[NN + 1];
__device__ int      g_cursor[NN];
__device__ unsigned long long g_lb[NB1];           // decoupled-lookback {value<<2|flag}
__device__ int2     g_epak[EMAX];                  // {src, bitcast(dinv[src])}
__device__ uint32_t g_mask[NMASKW];                // packed dropout keep-bits
__device__ __half   g_h1  [(size_t)NN * HD];       // gemm1 out (fp16, gathered by pull64)
__device__ float    g_agg1[(size_t)NN * HD];       // pull64+relu+dropout out (fp32)
__device__ __half   g_h2t [(size_t)NN * CD];       // gemm2 out (fp16, gathered by pull40)

// ---------------- threefry2x32 (bit-exact JAX partitionable path) ----------------
__device__ __forceinline__ uint32_t rotl32(uint32_t x, int d) {
    return __funnelshift_l(x, x, d);
}
__device__ __forceinline__ void tf_round(uint32_t& x0, uint32_t& x1, int r) {
    x0 += x1; x1 = rotl32(x1, r); x1 ^= x0;
}
__device__ __forceinline__ uint2 threefry_0_42(uint32_t x0, uint32_t x1) {
    const uint32_t k0 = 0u, k1 = 42u;
    const uint32_t k2 = 0u ^ 42u ^ 0x1BD11BDAu;
    x0 += k0; x1 += k1;
    tf_round(x0,x1,13); tf_round(x0,x1,15); tf_round(x0,x1,26); tf_round(x0,x1,6);
    x0 += k1; x1 += k2 + 1u;
    tf_round(x0,x1,17); tf_round(x0,x1,29); tf_round(x0,x1,16); tf_round(x0,x1,24);
    x0 += k2; x1 += k0 + 2u;
    tf_round(x0,x1,13); tf_round(x0,x1,15); tf_round(x0,x1,26); tf_round(x0,x1,6);
    x0 += k0; x1 += k1 + 3u;
    tf_round(x0,x1,17); tf_round(x0,x1,29); tf_round(x0,x1,16); tf_round(x0,x1,24);
    x0 += k1; x1 += k2 + 4u;
    tf_round(x0,x1,13); tf_round(x0,x1,15); tf_round(x0,x1,26); tf_round(x0,x1,6);
    x0 += k2; x1 += k0 + 5u;
    return make_uint2(x0, x1);
}

// ---------------- CSR: histogram ----------------
__global__ void hist_kernel(const int* __restrict__ col, int* __restrict__ cnt, int E) {
    int i = blockIdx.x * blockDim.x + threadIdx.x;
    if (i < E) atomicAdd(&cnt[col[i]], 1);
}

// ---------------- CSR: single-pass decoupled-lookback scan (+dinv, +cursor) ----------------
__global__ void scanlb_kernel(const int* __restrict__ cnt, int* __restrict__ rowptr,
                              int* __restrict__ cursor, float* __restrict__ dinv,
                              unsigned long long* lb, int n, int E) {
    __shared__ int s[SCAN_BS];
    __shared__ int bprefix;
    const int tid = threadIdx.x, b = blockIdx.x;
    const int gid = b * SCAN_BS + tid;
    int v = (gid < n) ? cnt[gid] : 0;
    s[tid] = v;
    __syncthreads();
    #pragma unroll
    for (int off = 1; off < SCAN_BS; off <<= 1) {
        int t = (tid >= off) ? s[tid - off] : 0;
        __syncthreads();
        s[tid] += t;
        __syncthreads();
    }
    int total = s[SCAN_BS - 1];
    if (tid == 0) {
        if (b == 0) {
            *(volatile unsigned long long*)&lb[0] =
                ((unsigned long long)total << 2) | FLAG_P;
            bprefix = 0;
        } else {
            *(volatile unsigned long long*)&lb[b] =
                ((unsigned long long)total << 2) | FLAG_A;
            int running = 0;
            int i = b - 1;
            while (true) {
                unsigned long long w;
                do { w = *(volatile unsigned long long*)&lb[i]; } while ((w & 3ULL) == 0);
                if ((w & 3ULL) == FLAG_P) { running += (int)(w >> 2); break; }
                running += (int)(w >> 2);
                i--;
            }
            *(volatile unsigned long long*)&lb[b] =
                ((unsigned long long)(running + total) << 2) | FLAG_P;
            bprefix = running;
        }
    }
    __syncthreads();
    int excl = bprefix + s[tid] - v;
    if (gid < n) {
        rowptr[gid] = excl;
        cursor[gid] = excl;
        dinv[gid]   = (float)(1.0 / sqrt((double)(v + 1)));   // +1 self loop
    }
    if (gid == 0) rowptr[n] = E;
}

// ---------------- CSR fill + dropout mask precompute (fused, disjoint ranges) ----------------
__global__ void fillmask_kernel(const int* __restrict__ row, const int* __restrict__ col,
                                const float* __restrict__ dinv,
                                int* __restrict__ cursor, int2* __restrict__ epak,
                                uint32_t* __restrict__ mask, int E) {
    int e = blockIdx.x * blockDim.x + threadIdx.x;
    if (e < NMASKB) {           // one mask byte (8 elements) per thread
        const float KEEP = (float)(1.0 - 0.4144);
        uint32_t base = (uint32_t)e * 8u;
        uint32_t byte = 0;
        #pragma unroll
        for (int b = 0; b < 8; b++) {
            uint2 rnd = threefry_0_42(0u, base + (uint32_t)b);
            uint32_t bits = rnd.x ^ rnd.y;
            float u = __uint_as_float((bits >> 9) | 0x3f800000u) - 1.0f;
            byte |= (u < KEEP ? 1u : 0u) << b;
        }
        ((uint8_t*)mask)[e] = (uint8_t)byte;
    }
    if (e < E) {
        int r = row[e], c = col[e];
        int pos = atomicAdd(&cursor[c], 1);
        epak[pos] = make_int2(r, __float_as_int(dinv[r]));
    }
}

// ---------------- GEMM1: h1[n,64](fp16) = X[n,128] @ W1[128,64] ----------------
__global__ __launch_bounds__(256)
void gemm1_kernel(const float* __restrict__ X, const float* __restrict__ W,
                  __half* __restrict__ Y, int n) {
    extern __shared__ float smem[];
    float (*sX)[FIN] = (float(*)[FIN])smem;              // 32KB
    float (*sW)[HD]  = (float(*)[HD])(smem + 64 * FIN);  // 32KB
    const int tid = threadIdx.x;
    const int m0  = blockIdx.x * 64;

    for (int i = tid; i < FIN * HD / 4; i += 256)
        ((float4*)sW)[i] = ((const float4*)W)[i];
    for (int i = tid; i < 64 * (FIN / 4); i += 256) {
        int rr = i >> 5;
        int kv = (i & 31) * 4;
        int row = m0 + rr;
        float4 v = (row < n) ? *(const float4*)&X[(size_t)row * FIN + kv]
                             : make_float4(0.f, 0.f, 0.f, 0.f);
        *(float4*)&sX[rr][kv] = v;
    }
    __syncthreads();

    const int tx = tid & 15, ty = tid >> 4;
    const int c0 = tx * 4, r0 = ty * 4;
    float acc[4][4] = {};
    #pragma unroll 8
    for (int k4 = 0; k4 < FIN; k4 += 4) {
        float4 xr[4];
        #pragma unroll
        for (int i = 0; i < 4; i++) xr[i] = *(const float4*)&sX[r0 + i][k4];
        #pragma unroll
        for (int kk = 0; kk < 4; kk++) {
            float4 wv = *(const float4*)&sW[k4 + kk][c0];
            #pragma unroll
            for (int i = 0; i < 4; i++) {
                float xs = ((const float*)&xr[i])[kk];
                acc[i][0] += xs * wv.x; acc[i][1] += xs * wv.y;
                acc[i][2] += xs * wv.z; acc[i][3] += xs * wv.w;
            }
        }
    }
    #pragma unroll
    for (int i = 0; i < 4; i++) {
        int row = m0 + r0 + i;
        if (row < n) {
            __half2 p0 = __floats2half2_rn(acc[i][0], acc[i][1]);
            __half2 p1 = __floats2half2_rn(acc[i][2], acc[i][3]);
            uint2 u = make_uint2(*(uint32_t*)&p0, *(uint32_t*)&p1);
            *(uint2*)&Y[(size_t)row * HD + c0] = u;
        }
    }
}

// ---------------- GEMM2: h2t[n,40](fp16) = agg1[n,64](fp32) @ W2[64,40] ----------------
__global__ __launch_bounds__(320)
void gemm2_kernel(const float* __restrict__ X, const float* __restrict__ W,
                  __half* __restrict__ Y, int n) {
    __shared__ float sX[128][HD];    // 32KB
    __shared__ float sW[HD][CD];     // 10KB
    const int tid = threadIdx.x;
    const int m0  = blockIdx.x * 128;

    for (int i = tid; i < HD * CD / 4; i += 320)
        ((float4*)sW)[i] = ((const float4*)W)[i];
    for (int i = tid; i < 128 * (HD / 4); i += 320) {
        int rr = i >> 4;
        int kv = (i & 15) * 4;
        int row = m0 + rr;
        float4 v = (row < n) ? *(const float4*)&X[(size_t)row * HD + kv]
                             : make_float4(0.f, 0.f, 0.f, 0.f);
        *(float4*)&sX[rr][kv] = v;
    }
    __syncthreads();

    const int tx = tid % 10, ty = tid / 10;
    const int c0 = tx * 4, r0 = ty * 4;
    float acc[4][4] = {};
    #pragma unroll 4
    for (int k4 = 0; k4 < HD; k4 += 4) {
        float4 xr[4];
        #pragma unroll
        for (int i = 0; i < 4; i++) xr[i] = *(const float4*)&sX[r0 + i][k4];
        #pragma unroll
        for (int kk = 0; kk < 4; kk++) {
            float4 wv = *(const float4*)&sW[k4 + kk][c0];
            #pragma unroll
            for (int i = 0; i < 4; i++) {
                float xs = ((const float*)&xr[i])[kk];
                acc[i][0] += xs * wv.x; acc[i][1] += xs * wv.y;
                acc[i][2] += xs * wv.z; acc[i][3] += xs * wv.w;
            }
        }
    }
    #pragma unroll
    for (int i = 0; i < 4; i++) {
        int row = m0 + r0 + i;
        if (row < n) {
            __half2 p0 = __floats2half2_rn(acc[i][0], acc[i][1]);
            __half2 p1 = __floats2half2_rn(acc[i][2], acc[i][3]);
            uint2 u = make_uint2(*(uint32_t*)&p0, *(uint32_t*)&p1);
            *(uint2*)&Y[(size_t)row * CD + c0] = u;
        }
    }
}

// ---------------- pull64: warp-cooperative edge staging + relu + mask dropout ----------------
__global__ __launch_bounds__(256)
void pull64_kernel(const int* __restrict__ rowptr, const int2* __restrict__ epak,
                   const float* __restrict__ dinv, const __half* __restrict__ h,
                   const float* __restrict__ bias, const uint32_t* __restrict__ mask,
                   float* __restrict__ out, int n) {
    int wid  = (blockIdx.x * blockDim.x + threadIdx.x) >> 5;
    int lane = threadIdx.x & 31;
    if (wid >= n) return;
    const int node = wid;
    const __half2* hh = (const __half2*)h;         // 32 half2 per row
    float wn = dinv[node];
    float2 acc = *(const float2*)&bias[lane * 2];
    {
        float2 hv = __half22float2(hh[(size_t)node * 32 + lane]);
        acc.x += wn * wn * hv.x;
        acc.y += wn * wn * hv.y;
    }
    const int s = rowptr[node], e = rowptr[node + 1];
    for (int base = s; base < e; base += 32) {
        int m = min(32, e - base);
        int2 p = make_int2(0, 0);
        if (lane < m) p = epak[base + lane];       // ONE coalesced edge-record load
        for (int k = 0; k < m; k++) {
            int   src = __shfl_sync(0xffffffffu, p.x, k);
            float w   = __int_as_float(__shfl_sync(0xffffffffu, p.y, k)) * wn;
            float2 v  = __half22float2(hh[(size_t)src * 32 + lane]);
            acc.x += w * v.x;
            acc.y += w * v.y;
        }
    }
    // relu + dropout via precomputed bit mask
    const float KEEP = (float)(1.0 - 0.4144);
    uint32_t wbits = mask[node * 2 + (lane >> 4)];
    int b = (lane * 2) & 31;
    acc.x = (wbits >> b)       & 1u ? fmaxf(acc.x, 0.0f) / KEEP : 0.0f;
    acc.y = (wbits >> (b + 1)) & 1u ? fmaxf(acc.y, 0.0f) / KEEP : 0.0f;
    *(float2*)&out[(size_t)node * HD + lane * 2] = acc;
}

// ---------------- pull40: warp-cooperative edge staging + log_softmax ----------------
__global__ __launch_bounds__(256)
void pull40_kernel(const int* __restrict__ rowptr, const int2* __restrict__ epak,
                   const float* __restrict__ dinv, const __half* __restrict__ h,
                   const float* __restrict__ bias, float* __restrict__ out, int n) {
    int wid  = (blockIdx.x * blockDim.x + threadIdx.x) >> 5;
    int lane = threadIdx.x & 31;
    if (wid >= n) return;
    const int node = wid;
    const bool act = lane < CD / 2;                // 20 active lanes
    const __half2* hh = (const __half2*)h;         // 20 half2 per row
    float wn = dinv[node];
    float2 acc = make_float2(0.f, 0.f);
    if (act) {
        acc = *(const float2*)&bias[lane * 2];
        float2 hv = __half22float2(hh[(size_t)node * 20 + lane]);
        acc.x += wn * wn * hv.x;
        acc.y += wn * wn * hv.y;
    }
    const int s = rowptr[node], e = rowptr[node + 1];
    for (int base = s; base < e; base += 32) {
        int m = min(32, e - base);
        int2 p = make_int2(0, 0);
        if (lane < m) p = epak[base + lane];       // ONE coalesced edge-record load
        for (int k = 0; k < m; k++) {
            int   src = __shfl_sync(0xffffffffu, p.x, k);
            float w   = __int_as_float(__shfl_sync(0xffffffffu, p.y, k)) * wn;
            if (act) {
                float2 v = __half22float2(hh[(size_t)src * 20 + lane]);
                acc.x += w * v.x;
                acc.y += w * v.y;
            }
        }
    }
    float m = act ? fmaxf(acc.x, acc.y) : -3.4e38f;
    #pragma unroll
    for (int o = 16; o; o >>= 1) m = fmaxf(m, __shfl_xor_sync(0xffffffffu, m, o));
    float sE = act ? (expf(acc.x - m) + expf(acc.y - m)) : 0.0f;
    #pragma unroll
    for (int o = 16; o; o >>= 1) sE += __shfl_xor_sync(0xffffffffu, sE, o);
    float ls = logf(sE);
    if (act)
        *(float2*)&out[(size_t)node * CD + lane * 2] =
            make_float2(acc.x - m - ls, acc.y - m - ls);
}

// ---------------- launch ----------------
extern "C" void kernel_launch(void* const* d_in, const int* in_sizes, int n_in,
                              void* d_out, int out_size) {
    const float* x  = (const float*)d_in[0];
    const int*   ei = (const int*)  d_in[1];
    const float* W1 = (const float*)d_in[2];
    const float* b1 = (const float*)d_in[3];
    const float* W2 = (const float*)d_in[4];
    const float* b2 = (const float*)d_in[5];
    float* out = (float*)d_out;

    const int n = NN;
    const int E = in_sizes[1] / 2;
    const int* row = ei;
    const int* col = ei + E;

    float *dinv, *agg1;
    __half *h1, *h2t;
    int *cnt, *rowptr, *cursor;
    unsigned long long *lb;
    int2 *epak;
    uint32_t *mask;
    cudaGetSymbolAddress((void**)&dinv,   g_dinv);
    cudaGetSymbolAddress((void**)&cnt,    g_cnt);
    cudaGetSymbolAddress((void**)&rowptr, g_rowptr);
    cudaGetSymbolAddress((void**)&cursor, g_cursor);
    cudaGetSymbolAddress((void**)&lb,     g_lb);
    cudaGetSymbolAddress((void**)&epak,   g_epak);
    cudaGetSymbolAddress((void**)&mask,   g_mask);
    cudaGetSymbolAddress((void**)&h1,     g_h1);
    cudaGetSymbolAddress((void**)&agg1,   g_agg1);
    cudaGetSymbolAddress((void**)&h2t,    g_h2t);

    static cudaStream_t s_csr = 0;
    static cudaEvent_t  e_fork = 0, e_join = 0;
    if (!s_csr) {
        cudaStreamCreateWithFlags(&s_csr, cudaStreamNonBlocking);
        cudaEventCreateWithFlags(&e_fork, cudaEventDisableTiming);
        cudaEventCreateWithFlags(&e_join, cudaEventDisableTiming);
        cudaFuncSetAttribute(gemm1_kernel,
                             cudaFuncAttributeMaxDynamicSharedMemorySize, GEMM1_SMEM);
    }

    const int T = 256;
    auto cdiv = [](long long a, long long b) { return (int)((a + b - 1) / b); };

    // ---- fork: CSR build + dropout mask on side stream, gemm1 on main stream ----
    cudaEventRecord(e_fork, 0);
    cudaStreamWaitEvent(s_csr, e_fork, 0);

    cudaMemsetAsync(cnt, 0, NN * sizeof(int), s_csr);
    cudaMemsetAsync(lb,  0, NB1 * sizeof(unsigned long long), s_csr);
    hist_kernel    <<<cdiv(E, T), T, 0, s_csr>>>(col, cnt, E);
    scanlb_kernel  <<<NB1, SCAN_BS, 0, s_csr>>>(cnt, rowptr, cursor, dinv, lb, n, E);
    fillmask_kernel<<<cdiv(E, T), T, 0, s_csr>>>(row, col, dinv, cursor, epak, mask, E);
    cudaEventRecord(e_join, s_csr);

    gemm1_kernel<<<cdiv(n, 64), 256, GEMM1_SMEM>>>(x, W1, h1, n);

    // ---- join, then the dependent chain on the main stream ----
    cudaStreamWaitEvent(0, e_join, 0);
    pull64_kernel<<<cdiv((long long)n * 32, T), T>>>(rowptr, epak, dinv, h1, b1, mask, agg1, n);
    gemm2_kernel<<<cdiv(n, 128), 320>>>(agg1, W2, h2t, n);
    pull40_kernel<<<cdiv((long long)n * 32, T), T>>>(rowptr, epak, dinv, h2t, b2, out, n);
}

// round 13
// speedup vs baseline: 2.6356x; 1.0374x over previous
#include <cuda_runtime.h>
#include <cuda_fp16.h>
#include <stdint.h>
#include <stddef.h>

#define NN    100000
#define EMAX  1600000
#define FIN   128
#define HD    64
#define CD    40

#define SCAN_BS   512
#define NB1       ((NN + SCAN_BS - 1) / SCAN_BS)   // 196
#define NMASKW    ((NN * HD) / 32)                  // 200,000 packed mask words
#define NMASKB    (NN * HD / 8)                     // 800,000 mask bytes

#define FLAG_A 1ULL
#define FLAG_P 2ULL

#define APAD 136    // halves per sA/sB row (128 + 8 pad -> conflict-free fragments)

// ---------------- scratch (static device globals; no allocation) ----------------
__device__ float    g_dinv[NN];
__device__ int      g_cnt [NN];
__device__ int      g_rowptr[NN + 1];
__device__ int      g_cursor[NN];
__device__ unsigned long long g_lb[NB1];           // decoupled-lookback {value<<2|flag}
__device__ int2     g_epak[EMAX];                  // {src, bitcast(dinv[src])}
__device__ uint32_t g_mask[NMASKW];                // packed dropout keep-bits
__device__ __half   g_h1  [(size_t)NN * HD];       // gemm1 out (fp16, gathered by pull64)
__device__ __half   g_h2t [(size_t)NN * CD];       // pull64-fused-gemm2 out (fp16)

// ---------------- threefry2x32 (bit-exact JAX partitionable path) ----------------
__device__ __forceinline__ uint32_t rotl32(uint32_t x, int d) {
    return __funnelshift_l(x, x, d);
}
__device__ __forceinline__ void tf_round(uint32_t& x0, uint32_t& x1, int r) {
    x0 += x1; x1 = rotl32(x1, r); x1 ^= x0;
}
__device__ __forceinline__ uint2 threefry_0_42(uint32_t x0, uint32_t x1) {
    const uint32_t k0 = 0u, k1 = 42u;
    const uint32_t k2 = 0u ^ 42u ^ 0x1BD11BDAu;
    x0 += k0; x1 += k1;
    tf_round(x0,x1,13); tf_round(x0,x1,15); tf_round(x0,x1,26); tf_round(x0,x1,6);
    x0 += k1; x1 += k2 + 1u;
    tf_round(x0,x1,17); tf_round(x0,x1,29); tf_round(x0,x1,16); tf_round(x0,x1,24);
    x0 += k2; x1 += k0 + 2u;
    tf_round(x0,x1,13); tf_round(x0,x1,15); tf_round(x0,x1,26); tf_round(x0,x1,6);
    x0 += k0; x1 += k1 + 3u;
    tf_round(x0,x1,17); tf_round(x0,x1,29); tf_round(x0,x1,16); tf_round(x0,x1,24);
    x0 += k1; x1 += k2 + 4u;
    tf_round(x0,x1,13); tf_round(x0,x1,15); tf_round(x0,x1,26); tf_round(x0,x1,6);
    x0 += k2; x1 += k0 + 5u;
    return make_uint2(x0, x1);
}

// ---------------- CSR: histogram ----------------
__global__ void hist_kernel(const int* __restrict__ col, int* __restrict__ cnt, int E) {
    int i = blockIdx.x * blockDim.x + threadIdx.x;
    if (i < E) atomicAdd(&cnt[col[i]], 1);
}

// ---------------- CSR: single-pass decoupled-lookback scan (+dinv, +cursor) ----------------
__global__ void scanlb_kernel(const int* __restrict__ cnt, int* __restrict__ rowptr,
                              int* __restrict__ cursor, float* __restrict__ dinv,
                              unsigned long long* lb, int n, int E) {
    __shared__ int s[SCAN_BS];
    __shared__ int bprefix;
    const int tid = threadIdx.x, b = blockIdx.x;
    const int gid = b * SCAN_BS + tid;
    int v = (gid < n) ? cnt[gid] : 0;
    s[tid] = v;
    __syncthreads();
    #pragma unroll
    for (int off = 1; off < SCAN_BS; off <<= 1) {
        int t = (tid >= off) ? s[tid - off] : 0;
        __syncthreads();
        s[tid] += t;
        __syncthreads();
    }
    int total = s[SCAN_BS - 1];
    if (tid == 0) {
        if (b == 0) {
            *(volatile unsigned long long*)&lb[0] =
                ((unsigned long long)total << 2) | FLAG_P;
            bprefix = 0;
        } else {
            *(volatile unsigned long long*)&lb[b] =
                ((unsigned long long)total << 2) | FLAG_A;
            int running = 0;
            int i = b - 1;
            while (true) {
                unsigned long long w;
                do { w = *(volatile unsigned long long*)&lb[i]; } while ((w & 3ULL) == 0);
                if ((w & 3ULL) == FLAG_P) { running += (int)(w >> 2); break; }
                running += (int)(w >> 2);
                i--;
            }
            *(volatile unsigned long long*)&lb[b] =
                ((unsigned long long)(running + total) << 2) | FLAG_P;
            bprefix = running;
        }
    }
    __syncthreads();
    int excl = bprefix + s[tid] - v;
    if (gid < n) {
        rowptr[gid] = excl;
        cursor[gid] = excl;
        dinv[gid]   = (float)(1.0 / sqrt((double)(v + 1)));   // +1 self loop
    }
    if (gid == 0) rowptr[n] = E;
}

// ---------------- CSR fill + dropout mask precompute (fused, disjoint ranges) ----------------
__global__ void fillmask_kernel(const int* __restrict__ row, const int* __restrict__ col,
                                const float* __restrict__ dinv,
                                int* __restrict__ cursor, int2* __restrict__ epak,
                                uint32_t* __restrict__ mask, int E) {
    int e = blockIdx.x * blockDim.x + threadIdx.x;
    if (e < NMASKB) {           // one mask byte (8 elements) per thread
        const float KEEP = (float)(1.0 - 0.4144);
        uint32_t base = (uint32_t)e * 8u;
        uint32_t byte = 0;
        #pragma unroll
        for (int b = 0; b < 8; b++) {
            uint2 rnd = threefry_0_42(0u, base + (uint32_t)b);
            uint32_t bits = rnd.x ^ rnd.y;
            float u = __uint_as_float((bits >> 9) | 0x3f800000u) - 1.0f;
            byte |= (u < KEEP ? 1u : 0u) << b;
        }
        ((uint8_t*)mask)[e] = (uint8_t)byte;
    }
    if (e < E) {
        int r = row[e], c = col[e];
        int pos = atomicAdd(&cursor[c], 1);
        epak[pos] = make_int2(r, __float_as_int(dinv[r]));
    }
}

// ---------------- GEMM1 (tensor core): h1[n,64](fp16) = X[n,128] @ W1[128,64] ----------------
// BM=64 rows/block, 256 threads = 8 warps. mma.sync m16n8k16 f16xf16->f32.
// Warp w: M-subtile mW=w&3 (16 rows), N-half nW=w>>2 (32 cols = 4 n-subtiles of 8).
__global__ __launch_bounds__(256)
void gemm1_kernel(const float* __restrict__ X, const float* __restrict__ W,
                  __half* __restrict__ Y, int n) {
    __shared__ __half sA[64][APAD];   // X tile, row-major [m][k]
    __shared__ __half sB[64][APAD];   // W1 transposed [nCol][k]
    const int tid = threadIdx.x;
    const int m0  = blockIdx.x * 64;

    // load X tile (fp32 -> fp16)
    for (int i = tid; i < 64 * (FIN / 4); i += 256) {
        int rr = i >> 5;
        int kv = (i & 31) * 4;
        int rowg = m0 + rr;
        float4 v = (rowg < n) ? *(const float4*)&X[(size_t)rowg * FIN + kv]
                              : make_float4(0.f, 0.f, 0.f, 0.f);
        __half2 h0 = __floats2half2_rn(v.x, v.y);
        __half2 h1v = __floats2half2_rn(v.z, v.w);
        *(uint2*)&sA[rr][kv] = make_uint2(*(uint32_t*)&h0, *(uint32_t*)&h1v);
    }
    // load W1 transposed (coalesced global read, scattered 2B smem write; once per block)
    for (int i = tid; i < FIN * HD; i += 256) {
        int k = i >> 6, c = i & 63;
        sB[c][k] = __float2half_rn(W[i]);
    }
    __syncthreads();

    const int w    = tid >> 5;
    const int lane = tid & 31;
    const int mW = (w & 3) * 16;
    const int nW = (w >> 2) * 32;
    const int g  = lane >> 2;      // 0..7
    const int tg = lane & 3;       // 0..3

    float d[4][4];
    #pragma unroll
    for (int s = 0; s < 4; s++)
        d[s][0] = d[s][1] = d[s][2] = d[s][3] = 0.f;

    const uint32_t* rowA0 = (const uint32_t*)&sA[mW + g][0];      // half2-indexed
    const uint32_t* rowA8 = (const uint32_t*)&sA[mW + g + 8][0];

    #pragma unroll
    for (int ks = 0; ks < 8; ks++) {
        int k2 = ks * 8;                    // half2 index of k0 = ks*16
        uint32_t a0 = rowA0[k2 + tg];
        uint32_t a1 = rowA8[k2 + tg];
        uint32_t a2 = rowA0[k2 + tg + 4];
        uint32_t a3 = rowA8[k2 + tg + 4];
        #pragma unroll
        for (int s = 0; s < 4; s++) {
            const uint32_t* rowB = (const uint32_t*)&sB[nW + s * 8 + g][0];
            uint32_t b0 = rowB[k2 + tg];
            uint32_t b1 = rowB[k2 + tg + 4];
            asm volatile(
                "mma.sync.aligned.m16n8k16.row.col.f32.f16.f16.f32 "
                "{%0,%1,%2,%3}, {%4,%5,%6,%7}, {%8,%9}, {%0,%1,%2,%3};\n"
                : "+f"(d[s][0]), "+f"(d[s][1]), "+f"(d[s][2]), "+f"(d[s][3])
                : "r"(a0), "r"(a1), "r"(a2), "r"(a3), "r"(b0), "r"(b1));
        }
    }

    // store: d0,d1 -> row g,   cols tg*2,+1 ; d2,d3 -> row g+8
    #pragma unroll
    for (int s = 0; s < 4; s++) {
        int c = nW + s * 8 + tg * 2;
        int r0 = m0 + mW + g;
        int r1 = r0 + 8;
        if (r0 < n) {
            __half2 p = __floats2half2_rn(d[s][0], d[s][1]);
            *(uint32_t*)&Y[(size_t)r0 * HD + c] = *(uint32_t*)&p;
        }
        if (r1 < n) {
            __half2 p = __floats2half2_rn(d[s][2], d[s][3]);
            *(uint32_t*)&Y[(size_t)r1 * HD + c] = *(uint32_t*)&p;
        }
    }
}

// ---------------- pull64 + relu + mask dropout + FUSED GEMM2 -> h2t fp16 ----------------
// Per warp (one node): aggregate 64 feats, relu+dropout, then z = a @ W2 (64x40) in-warp.
__global__ __launch_bounds__(256)
void pull64_kernel(const int* __restrict__ rowptr, const int2* __restrict__ epak,
                   const float* __restrict__ dinv, const __half* __restrict__ h,
                   const float* __restrict__ bias, const uint32_t* __restrict__ mask,
                   const float* __restrict__ W2, __half* __restrict__ out, int n) {
    __shared__ float sW2[HD][CD];     // 10KB
    __shared__ float sAr[8][HD + 2];  // per-warp staging of a-row
    const int tid = threadIdx.x;
    for (int i = tid; i < HD * CD; i += 256) sW2[i / CD][i % CD] = W2[i];
    __syncthreads();

    int wid  = (blockIdx.x * blockDim.x + tid) >> 5;
    int lane = tid & 31;
    int wl   = tid >> 5;              // warp within block
    if (wid >= n) return;
    const int node = wid;
    const __half2* hh = (const __half2*)h;         // 32 half2 per row
    float wn = dinv[node];
    float2 acc = *(const float2*)&bias[lane * 2];
    {
        float2 hv = __half22float2(hh[(size_t)node * 32 + lane]);
        acc.x += wn * wn * hv.x;
        acc.y += wn * wn * hv.y;
    }
    const int s = rowptr[node], e = rowptr[node + 1];
    for (int base = s; base < e; base += 32) {
        int m = min(32, e - base);
        int2 p = make_int2(0, 0);
        if (lane < m) p = epak[base + lane];       // ONE coalesced edge-record load
        for (int k = 0; k < m; k++) {
            int   src = __shfl_sync(0xffffffffu, p.x, k);
            float wv  = __int_as_float(__shfl_sync(0xffffffffu, p.y, k)) * wn;
            float2 v  = __half22float2(hh[(size_t)src * 32 + lane]);
            acc.x += wv * v.x;
            acc.y += wv * v.y;
        }
    }
    // relu + dropout via precomputed bit mask
    const float KEEP = (float)(1.0 - 0.4144);
    uint32_t wbits = mask[node * 2 + (lane >> 4)];
    int b = (lane * 2) & 31;
    acc.x = (wbits >> b)       & 1u ? fmaxf(acc.x, 0.0f) / KEEP : 0.0f;
    acc.y = (wbits >> (b + 1)) & 1u ? fmaxf(acc.y, 0.0f) / KEEP : 0.0f;

    // fused gemm2: stage a-row, lanes 0..19 compute 2 output cols each
    *(float2*)&sAr[wl][lane * 2] = acc;
    __syncwarp();
    if (lane < CD / 2) {
        const int c0 = lane * 2;
        float2 o = make_float2(0.f, 0.f);
        #pragma unroll 8
        for (int k = 0; k < HD; k++) {
            float ak = sAr[wl][k];
            float2 wv = *(const float2*)&sW2[k][c0];
            o.x += ak * wv.x;
            o.y += ak * wv.y;
        }
        __half2 p = __floats2half2_rn(o.x, o.y);
        *(uint32_t*)&out[(size_t)node * CD + c0] = *(uint32_t*)&p;
    }
}

// ---------------- pull40: warp-cooperative edge staging + log_softmax ----------------
__global__ __launch_bounds__(256)
void pull40_kernel(const int* __restrict__ rowptr, const int2* __restrict__ epak,
                   const float* __restrict__ dinv, const __half* __restrict__ h,
                   const float* __restrict__ bias, float* __restrict__ out, int n) {
    int wid  = (blockIdx.x * blockDim.x + threadIdx.x) >> 5;
    int lane = threadIdx.x & 31;
    if (wid >= n) return;
    const int node = wid;
    const bool act = lane < CD / 2;                // 20 active lanes
    const __half2* hh = (const __half2*)h;         // 20 half2 per row
    float wn = dinv[node];
    float2 acc = make_float2(0.f, 0.f);
    if (act) {
        acc = *(const float2*)&bias[lane * 2];
        float2 hv = __half22float2(hh[(size_t)node * 20 + lane]);
        acc.x += wn * wn * hv.x;
        acc.y += wn * wn * hv.y;
    }
    const int s = rowptr[node], e = rowptr[node + 1];
    for (int base = s; base < e; base += 32) {
        int m = min(32, e - base);
        int2 p = make_int2(0, 0);
        if (lane < m) p = epak[base + lane];       // ONE coalesced edge-record load
        for (int k = 0; k < m; k++) {
            int   src = __shfl_sync(0xffffffffu, p.x, k);
            float w   = __int_as_float(__shfl_sync(0xffffffffu, p.y, k)) * wn;
            if (act) {
                float2 v = __half22float2(hh[(size_t)src * 20 + lane]);
                acc.x += w * v.x;
                acc.y += w * v.y;
            }
        }
    }
    float m = act ? fmaxf(acc.x, acc.y) : -3.4e38f;
    #pragma unroll
    for (int o = 16; o; o >>= 1) m = fmaxf(m, __shfl_xor_sync(0xffffffffu, m, o));
    float sE = act ? (expf(acc.x - m) + expf(acc.y - m)) : 0.0f;
    #pragma unroll
    for (int o = 16; o; o >>= 1) sE += __shfl_xor_sync(0xffffffffu, sE, o);
    float ls = logf(sE);
    if (act)
        *(float2*)&out[(size_t)node * CD + lane * 2] =
            make_float2(acc.x - m - ls, acc.y - m - ls);
}

// ---------------- launch ----------------
extern "C" void kernel_launch(void* const* d_in, const int* in_sizes, int n_in,
                              void* d_out, int out_size) {
    const float* x  = (const float*)d_in[0];
    const int*   ei = (const int*)  d_in[1];
    const float* W1 = (const float*)d_in[2];
    const float* b1 = (const float*)d_in[3];
    const float* W2 = (const float*)d_in[4];
    const float* b2 = (const float*)d_in[5];
    float* out = (float*)d_out;

    const int n = NN;
    const int E = in_sizes[1] / 2;
    const int* row = ei;
    const int* col = ei + E;

    float *dinv;
    __half *h1, *h2t;
    int *cnt, *rowptr, *cursor;
    unsigned long long *lb;
    int2 *epak;
    uint32_t *mask;
    cudaGetSymbolAddress((void**)&dinv,   g_dinv);
    cudaGetSymbolAddress((void**)&cnt,    g_cnt);
    cudaGetSymbolAddress((void**)&rowptr, g_rowptr);
    cudaGetSymbolAddress((void**)&cursor, g_cursor);
    cudaGetSymbolAddress((void**)&lb,     g_lb);
    cudaGetSymbolAddress((void**)&epak,   g_epak);
    cudaGetSymbolAddress((void**)&mask,   g_mask);
    cudaGetSymbolAddress((void**)&h1,     g_h1);
    cudaGetSymbolAddress((void**)&h2t,    g_h2t);

    static cudaStream_t s_csr = 0;
    static cudaEvent_t  e_fork = 0, e_join = 0;
    if (!s_csr) {
        cudaStreamCreateWithFlags(&s_csr, cudaStreamNonBlocking);
        cudaEventCreateWithFlags(&e_fork, cudaEventDisableTiming);
        cudaEventCreateWithFlags(&e_join, cudaEventDisableTiming);
    }

    const int T = 256;
    auto cdiv = [](long long a, long long b) { return (int)((a + b - 1) / b); };

    // ---- fork: CSR build + dropout mask on side stream, gemm1 on main stream ----
    cudaEventRecord(e_fork, 0);
    cudaStreamWaitEvent(s_csr, e_fork, 0);

    cudaMemsetAsync(cnt, 0, NN * sizeof(int), s_csr);
    cudaMemsetAsync(lb,  0, NB1 * sizeof(unsigned long long), s_csr);
    hist_kernel    <<<cdiv(E, T), T, 0, s_csr>>>(col, cnt, E);
    scanlb_kernel  <<<NB1, SCAN_BS, 0, s_csr>>>(cnt, rowptr, cursor, dinv, lb, n, E);
    fillmask_kernel<<<cdiv(E, T), T, 0, s_csr>>>(row, col, dinv, cursor, epak, mask, E);
    cudaEventRecord(e_join, s_csr);

    gemm1_kernel<<<cdiv(n, 64), 256>>>(x, W1, h1, n);

    // ---- join, then the dependent chain on the main stream ----
    cudaStreamWaitEvent(0, e_join, 0);
    pull64_kernel<<<cdiv((long long)n * 32, T), T>>>(rowptr, epak, dinv, h1, b1, mask, W2, h2t, n);
    pull40_kernel<<<cdiv((long long)n * 32, T), T>>>(rowptr, epak, dinv, h2t, b2, out, n);
}